// round 14
// baseline (speedup 1.0000x reference)
#include <cuda_runtime.h>
#include <cuda_bf16.h>
#include <math.h>
#include <cstdint>

// ---------------- problem constants ----------------
#define BATCH   256
#define NTOK    65
#define BN_TOK  (BATCH*NTOK)      // 16640
#define DMODEL  1024
#define HEADS   16
#define HD      64
#define FF      4096
#define DEPTH   12
#define NPATCH  64
#define PSZ     32
#define IMGSZ   256
#define MPATCH  (BATCH*NPATCH)    // 16384

// ---------------- scratch ----------------
__device__ __align__(16) float g_x   [BN_TOK*DMODEL];
__device__ __align__(16) float g_qkv [BN_TOK*3*DMODEL];
__device__ __align__(16) float g_xp  [MPATCH*DMODEL];   // patch embed; later xc / xc2
__device__ __align__(16) float g_part[2*BN_TOK*DMODEL]; // split-K partials
__device__ __align__(16) __nv_bfloat16 g_Ahi[BN_TOK*DMODEL];
__device__ __align__(16) __nv_bfloat16 g_Alo[BN_TOK*DMODEL];
__device__ __align__(16) __nv_bfloat16 g_Mhi[BN_TOK*FF];
__device__ __align__(16) __nv_bfloat16 g_Mlo[BN_TOK*FF];
__device__ __align__(16) __nv_bfloat16 g_Bhi[DMODEL*DMODEL];   // patch weights only
__device__ __align__(16) __nv_bfloat16 g_Blo[DMODEL*DMODEL];

// per-layer pre-converted weights (side-stream targets)
__device__ __align__(16) __nv_bfloat16 g_Wqh[DEPTH*DMODEL*3*DMODEL];
__device__ __align__(16) __nv_bfloat16 g_Wql[DEPTH*DMODEL*3*DMODEL];
__device__ __align__(16) __nv_bfloat16 g_Wph[DEPTH*DMODEL*DMODEL];
__device__ __align__(16) __nv_bfloat16 g_Wpl[DEPTH*DMODEL*DMODEL];
__device__ __align__(16) __nv_bfloat16 g_W1h[DEPTH*DMODEL*FF];
__device__ __align__(16) __nv_bfloat16 g_W1l[DEPTH*DMODEL*FF];
__device__ __align__(16) __nv_bfloat16 g_W2h[DEPTH*FF*DMODEL];
__device__ __align__(16) __nv_bfloat16 g_W2l[DEPTH*FF*DMODEL];

// ---------------- PTX helpers (base-target sm_80+ only) ----------------
__device__ __forceinline__ uint32_t smem_u32(const void* p) {
    uint32_t a;
    asm("{ .reg .u64 t; cvta.to.shared.u64 t, %1; cvt.u32.u64 %0, t; }" : "=r"(a) : "l"(p));
    return a;
}
__device__ __forceinline__ void cpasync16(uint32_t dst, const void* src) {
    asm volatile("cp.async.cg.shared.global [%0], [%1], 16;" :: "r"(dst), "l"(src));
}
__device__ __forceinline__ void cpasync_commit() {
    asm volatile("cp.async.commit_group;" ::: "memory");
}
__device__ __forceinline__ void cpasync_wait0() {
    asm volatile("cp.async.wait_group 0;" ::: "memory");
}
__device__ __forceinline__ void cpasync_wait1() {
    asm volatile("cp.async.wait_group 1;" ::: "memory");
}
__device__ __forceinline__ void ldsm4(uint32_t* r, uint32_t addr) {
    asm volatile("ldmatrix.sync.aligned.m8n8.x4.shared.b16 {%0,%1,%2,%3}, [%4];"
                 : "=r"(r[0]), "=r"(r[1]), "=r"(r[2]), "=r"(r[3]) : "r"(addr));
}
__device__ __forceinline__ void mma16816(float* c, const uint32_t* a, const uint32_t* b) {
    asm volatile("mma.sync.aligned.m16n8k16.row.col.f32.bf16.bf16.f32 "
                 "{%0,%1,%2,%3}, {%4,%5,%6,%7}, {%8,%9}, {%0,%1,%2,%3};"
                 : "+f"(c[0]), "+f"(c[1]), "+f"(c[2]), "+f"(c[3])
                 : "r"(a[0]), "r"(a[1]), "r"(a[2]), "r"(a[3]), "r"(b[0]), "r"(b[1]));
}

// ---------------- small helpers ----------------
__device__ __forceinline__ float gelu_f(float v) {
    return 0.5f * v * (1.0f + erff(v * 0.70710678118654752440f));
}
__device__ __forceinline__ void store_hilo4(__nv_bfloat16* Hi, __nv_bfloat16* Lo, size_t idx, float4 v) {
    __nv_bfloat162 h0 = __floats2bfloat162_rn(v.x, v.y);
    __nv_bfloat162 h1 = __floats2bfloat162_rn(v.z, v.w);
    __nv_bfloat162 l0 = __floats2bfloat162_rn(v.x - __low2float(h0), v.y - __high2float(h0));
    __nv_bfloat162 l1 = __floats2bfloat162_rn(v.z - __low2float(h1), v.w - __high2float(h1));
    *reinterpret_cast<__nv_bfloat162*>(Hi + idx)     = h0;
    *reinterpret_cast<__nv_bfloat162*>(Hi + idx + 2) = h1;
    *reinterpret_cast<__nv_bfloat162*>(Lo + idx)     = l0;
    *reinterpret_cast<__nv_bfloat162*>(Lo + idx + 2) = l1;
}
__device__ __forceinline__ void store_hilo2(__nv_bfloat16* Hi, __nv_bfloat16* Lo, size_t idx, float v0, float v1) {
    __nv_bfloat162 h = __floats2bfloat162_rn(v0, v1);
    __nv_bfloat162 l = __floats2bfloat162_rn(v0 - __low2float(h), v1 - __high2float(h));
    *reinterpret_cast<__nv_bfloat162*>(Hi + idx) = h;
    *reinterpret_cast<__nv_bfloat162*>(Lo + idx) = l;
}
__device__ __forceinline__ void store_hilo1(__nv_bfloat16* Hi, __nv_bfloat16* Lo, size_t idx, float v) {
    __nv_bfloat16 h = __float2bfloat16(v);
    Hi[idx] = h;
    Lo[idx] = __float2bfloat16(v - __bfloat162float(h));
}

// ---------------- patch gather -> bf16 hi/lo rows [16384, 1024] ----------------
__global__ void gather_kernel(const float* __restrict__ img) {
    int idx = blockIdx.x * blockDim.x + threadIdx.x;
    const int total = MPATCH * PSZ * PSZ;
    if (idx >= total) return;
    int k = idx & 1023;
    int p = (idx >> 10) & 63;
    int b = idx >> 16;
    int i = k >> 5, j = k & 31;
    int gr = p >> 3, gc = p & 7;
    float v = img[(size_t)b*IMGSZ*IMGSZ + (size_t)(gr*PSZ + i)*IMGSZ + gc*PSZ + j];
    __nv_bfloat16 h = __float2bfloat16(v);
    g_Mhi[idx] = h;
    g_Mlo[idx] = __float2bfloat16(v - __bfloat162float(h));
}

// ---------------- assemble x = [cls ; patches] ----------------
__global__ void assemble_kernel(const float* __restrict__ cls) {
    int idx = blockIdx.x * blockDim.x + threadIdx.x;
    const int total = BN_TOK*DMODEL;
    if (idx >= total) return;
    int d = idx & 1023;
    int n = idx >> 10;
    int b = n / NTOK;
    int t = n - b*NTOK;
    g_x[idx] = (t == 0) ? cls[d] : g_xp[(size_t)(b*NPATCH + t - 1)*DMODEL + d];
}

// ---------------- weight transpose-convert: W[K,N] -> Bt[N,K] hi/lo bf16 ----------------
__global__ __launch_bounds__(256)
void wconv_kernel(const float* __restrict__ W, __nv_bfloat16* __restrict__ Bh,
                  __nv_bfloat16* __restrict__ Bl, int K, int N) {
    __shared__ float t[32][33];
    int n0 = blockIdx.x * 32, k0 = blockIdx.y * 32;
    int tx = threadIdx.x, ty = threadIdx.y;   // 32 x 8
#pragma unroll
    for (int i = 0; i < 32; i += 8)
        t[ty+i][tx] = W[(size_t)(k0+ty+i)*N + n0+tx];
    __syncthreads();
#pragma unroll
    for (int i = 0; i < 32; i += 8) {
        int n = ty + i;
        float v = t[tx][n];
        __nv_bfloat16 h = __float2bfloat16(v);
        size_t o = (size_t)(n0+n)*K + k0+tx;
        Bh[o] = h;
        Bl[o] = __float2bfloat16(v - __bfloat162float(h));
    }
}

// ---------------- mma.sync GEMM 128x128 (3xBF16 compensation) ----------------
// epi: 0 plain f32, 1 +bias, 2 +bias+residual, 3 +bias+gelu->hi/lo,
//      4 split-K partial: z-th gridDim.z slice computes K range
//        [z*Klen, (z+1)*Klen) and stores raw f32 at C + z*M*Nn.
#define TILEB  (128*64)                  // 8192 bytes per tile
#define STAGEB (4*TILEB)                 // 32768
#define NSTAGE 3
#define GEMM_SMEM (NSTAGE*STAGEB)        // 98304

__device__ __forceinline__ void load_stage(uint32_t sbase,
    const __nv_bfloat16* __restrict__ Ahi, const __nv_bfloat16* __restrict__ Alo,
    const __nv_bfloat16* __restrict__ Bhi, const __nv_bfloat16* __restrict__ Blo,
    int row0, int col0, int Kstride, int k0, int tid)
{
#pragma unroll
    for (int i = 0; i < 2; i++) {
        int c   = tid + i*256;
        int row = c >> 2, lc = c & 3;
        uint32_t soff = (uint32_t)(row*64 + ((lc ^ ((row>>1)&3))*16));
        size_t ga = (size_t)(row0 + row)*Kstride + k0 + lc*8;
        size_t gb = (size_t)(col0 + row)*Kstride + k0 + lc*8;
        cpasync16(sbase +            soff, Ahi + ga);
        cpasync16(sbase +   TILEB +  soff, Alo + ga);
        cpasync16(sbase + 2*TILEB +  soff, Bhi + gb);
        cpasync16(sbase + 3*TILEB +  soff, Blo + gb);
    }
    cpasync_commit();
}

__global__ __launch_bounds__(256, 2)
void gemm_mma(const __nv_bfloat16* __restrict__ Ahi, const __nv_bfloat16* __restrict__ Alo,
              const __nv_bfloat16* __restrict__ Bhi, const __nv_bfloat16* __restrict__ Blo,
              const float* __restrict__ bias, const float* __restrict__ res,
              float* __restrict__ C, __nv_bfloat16* __restrict__ Ohi, __nv_bfloat16* __restrict__ Olo,
              int M, int Nn, int Klen, int Kstride, int epi)
{
    extern __shared__ char smem[];
    uint32_t sb = smem_u32(smem);
    int tid = threadIdx.x;
    int wid = tid >> 5, lane = tid & 31;
    int row0 = blockIdx.y * 128, col0 = blockIdx.x * 128;
    int kbase = blockIdx.z * Klen;
    if (epi == 4) { C += (size_t)blockIdx.z * M * Nn; epi = 0; }

    int wm = (wid & 1) * 64;
    int wn = (wid >> 1) * 32;

    int aRow = wm + (lane & 15);
    uint32_t aSw  = (uint32_t)(((aRow >> 1) & 3) << 4);
    uint32_t aKB  = (uint32_t)(((lane >> 4) & 1) << 4);
    uint32_t aBase = (uint32_t)(aRow * 64);
    int bRow = wn + (lane & 7) + ((lane >> 4) & 1) * 8;
    uint32_t bSw  = (uint32_t)(((bRow >> 1) & 3) << 4);
    uint32_t bKB  = (uint32_t)(((lane >> 3) & 1) << 4);
    uint32_t bBase = (uint32_t)(bRow * 64);

    float acc[4][4][4];
#pragma unroll
    for (int mt = 0; mt < 4; mt++)
#pragma unroll
        for (int nt = 0; nt < 4; nt++)
#pragma unroll
            for (int e = 0; e < 4; e++) acc[mt][nt][e] = 0.f;

    int NC = Klen >> 5;
    load_stage(sb, Ahi, Alo, Bhi, Blo, row0, col0, Kstride, kbase, tid);
    if (NC > 1)
        load_stage(sb + STAGEB, Ahi, Alo, Bhi, Blo, row0, col0, Kstride, kbase + 32, tid);

    uint32_t stOff = 0;
    uint32_t ldOff = (NC > 1) ? 2u*STAGEB : STAGEB;

#pragma unroll 1
    for (int kc = 0; kc < NC; kc++) {
        if (kc + 1 < NC) cpasync_wait1(); else cpasync_wait0();
        __syncthreads();
        if (kc + 2 < NC) {
            load_stage(sb + ldOff, Ahi, Alo, Bhi, Blo, row0, col0, Kstride, kbase + ((kc + 2) << 5), tid);
        }
        uint32_t st = sb + stOff;
        stOff += STAGEB; if (stOff == NSTAGE*STAGEB) stOff = 0;
        ldOff += STAGEB; if (ldOff == NSTAGE*STAGEB) ldOff = 0;

#pragma unroll
        for (int ks2 = 0; ks2 < 2; ks2++) {
            uint32_t kadd = (uint32_t)ks2 * 32;
            uint32_t aLK = (kadd + aKB) ^ aSw;
            uint32_t bLK = (kadd + bKB) ^ bSw;
            uint32_t ah[4][4], bh[2][4], al[4][4], bl[2][4];
#pragma unroll
            for (int mt = 0; mt < 4; mt++)
                ldsm4(ah[mt], st + aBase + (uint32_t)mt*1024 + aLK);
#pragma unroll
            for (int ntp = 0; ntp < 2; ntp++)
                ldsm4(bh[ntp], st + 2*TILEB + bBase + (uint32_t)ntp*1024 + bLK);
#pragma unroll
            for (int mt = 0; mt < 4; mt++)
                ldsm4(al[mt], st + TILEB + aBase + (uint32_t)mt*1024 + aLK);
            // hi x hi
#pragma unroll
            for (int mt = 0; mt < 4; mt++)
#pragma unroll
                for (int nt = 0; nt < 4; nt++)
                    mma16816(acc[mt][nt], ah[mt], &bh[nt>>1][(nt&1)*2]);
#pragma unroll
            for (int ntp = 0; ntp < 2; ntp++)
                ldsm4(bl[ntp], st + 3*TILEB + bBase + (uint32_t)ntp*1024 + bLK);
            // lo x hi
#pragma unroll
            for (int mt = 0; mt < 4; mt++)
#pragma unroll
                for (int nt = 0; nt < 4; nt++)
                    mma16816(acc[mt][nt], al[mt], &bh[nt>>1][(nt&1)*2]);
            // hi x lo
#pragma unroll
            for (int mt = 0; mt < 4; mt++)
#pragma unroll
                for (int nt = 0; nt < 4; nt++)
                    mma16816(acc[mt][nt], ah[mt], &bl[nt>>1][(nt&1)*2]);
        }
    }

    // ---------------- epilogue ----------------
    int base_r = row0 + wm;
    int base_c = col0 + wn;
#pragma unroll
    for (int mt = 0; mt < 4; mt++) {
#pragma unroll
        for (int nt = 0; nt < 4; nt++) {
            int r = base_r + mt*16 + (lane >> 2);
            int c = base_c + nt*8 + (lane & 3)*2;
            float* a4 = acc[mt][nt];
#pragma unroll
            for (int half = 0; half < 2; half++) {
                int rr = r + half*8;
                float v0 = a4[half*2], v1 = a4[half*2+1];
                size_t off = (size_t)rr * Nn + c;
                if (epi != 0) {
                    float2 bb = *reinterpret_cast<const float2*>(bias + c);
                    v0 += bb.x; v1 += bb.y;
                }
                if (epi == 3) {
                    v0 = gelu_f(v0); v1 = gelu_f(v1);
                    store_hilo2(Ohi, Olo, off, v0, v1);
                } else {
                    if (epi == 2) {
                        float2 rr2 = *reinterpret_cast<const float2*>(res + off);
                        v0 += rr2.x; v1 += rr2.y;
                    }
                    float2 o; o.x = v0; o.y = v1;
                    *reinterpret_cast<float2*>(C + off) = o;
                }
            }
        }
    }
}

// ---------------- layernorm -> bf16 hi/lo ----------------
__global__ __launch_bounds__(128)
void ln_kernel(const float* __restrict__ x, const float* __restrict__ g,
               const float* __restrict__ b, __nv_bfloat16* __restrict__ Ohi,
               __nv_bfloat16* __restrict__ Olo)
{
    int row = blockIdx.x;
    int tid = threadIdx.x;
    const float* xp = x + (size_t)row * DMODEL;
    float4 a = *(const float4*)(xp + tid*4);
    float4 c = *(const float4*)(xp + 512 + tid*4);
    float s  = a.x+a.y+a.z+a.w + c.x+c.y+c.z+c.w;
    float sq = a.x*a.x+a.y*a.y+a.z*a.z+a.w*a.w + c.x*c.x+c.y*c.y+c.z*c.z+c.w*c.w;
#pragma unroll
    for (int off = 16; off; off >>= 1) {
        s  += __shfl_xor_sync(0xffffffffu, s,  off);
        sq += __shfl_xor_sync(0xffffffffu, sq, off);
    }
    __shared__ float sm[8];
    int wid = tid >> 5, lane = tid & 31;
    if (lane == 0) { sm[wid] = s; sm[4+wid] = sq; }
    __syncthreads();
    s  = sm[0]+sm[1]+sm[2]+sm[3];
    sq = sm[4]+sm[5]+sm[6]+sm[7];
    float mu  = s * (1.f/DMODEL);
    float var = sq * (1.f/DMODEL) - mu*mu;
    float inv = rsqrtf(var + 1e-5f);

    int d0 = tid*4;
    float4 g0 = *(const float4*)(g + d0);
    float4 b0 = *(const float4*)(b + d0);
    float4 o0;
    o0.x = (a.x-mu)*inv*g0.x + b0.x; o0.y = (a.y-mu)*inv*g0.y + b0.y;
    o0.z = (a.z-mu)*inv*g0.z + b0.z; o0.w = (a.w-mu)*inv*g0.w + b0.w;
    store_hilo4(Ohi, Olo, (size_t)row*DMODEL + d0, o0);

    int d1 = 512 + tid*4;
    float4 g1 = *(const float4*)(g + d1);
    float4 b1 = *(const float4*)(b + d1);
    float4 o1;
    o1.x = (c.x-mu)*inv*g1.x + b1.x; o1.y = (c.y-mu)*inv*g1.y + b1.y;
    o1.z = (c.z-mu)*inv*g1.z + b1.z; o1.w = (c.w-mu)*inv*g1.w + b1.w;
    store_hilo4(Ohi, Olo, (size_t)row*DMODEL + d1, o1);
}

// ---------------- fused split-K reduce + residual + layernorm ----------------
// x = x + P0 + P1 + b2; writes x back; then layernorm(x)*g+b -> hi/lo.
__global__ __launch_bounds__(128)
void ln_red_kernel(float* __restrict__ x, const float* __restrict__ P,
                   const float* __restrict__ b2,
                   const float* __restrict__ g, const float* __restrict__ b,
                   __nv_bfloat16* __restrict__ Ohi, __nv_bfloat16* __restrict__ Olo)
{
    int row = blockIdx.x;
    int tid = threadIdx.x;
    size_t rbase = (size_t)row * DMODEL;
    const float* P0 = P;
    const float* P1 = P + (size_t)BN_TOK * DMODEL;

    int d0 = tid*4, d1 = 512 + tid*4;
    float4 a  = *(const float4*)(x + rbase + d0);
    float4 c  = *(const float4*)(x + rbase + d1);
    float4 p0a = *(const float4*)(P0 + rbase + d0);
    float4 p0c = *(const float4*)(P0 + rbase + d1);
    float4 p1a = *(const float4*)(P1 + rbase + d0);
    float4 p1c = *(const float4*)(P1 + rbase + d1);
    float4 ba = *(const float4*)(b2 + d0);
    float4 bc = *(const float4*)(b2 + d1);
    a.x += p0a.x + p1a.x + ba.x; a.y += p0a.y + p1a.y + ba.y;
    a.z += p0a.z + p1a.z + ba.z; a.w += p0a.w + p1a.w + ba.w;
    c.x += p0c.x + p1c.x + bc.x; c.y += p0c.y + p1c.y + bc.y;
    c.z += p0c.z + p1c.z + bc.z; c.w += p0c.w + p1c.w + bc.w;
    *(float4*)(x + rbase + d0) = a;
    *(float4*)(x + rbase + d1) = c;

    float s  = a.x+a.y+a.z+a.w + c.x+c.y+c.z+c.w;
    float sq = a.x*a.x+a.y*a.y+a.z*a.z+a.w*a.w + c.x*c.x+c.y*c.y+c.z*c.z+c.w*c.w;
#pragma unroll
    for (int off = 16; off; off >>= 1) {
        s  += __shfl_xor_sync(0xffffffffu, s,  off);
        sq += __shfl_xor_sync(0xffffffffu, sq, off);
    }
    __shared__ float sm[8];
    int wid = tid >> 5, lane = tid & 31;
    if (lane == 0) { sm[wid] = s; sm[4+wid] = sq; }
    __syncthreads();
    s  = sm[0]+sm[1]+sm[2]+sm[3];
    sq = sm[4]+sm[5]+sm[6]+sm[7];
    float mu  = s * (1.f/DMODEL);
    float var = sq * (1.f/DMODEL) - mu*mu;
    float inv = rsqrtf(var + 1e-5f);

    float4 g0 = *(const float4*)(g + d0);
    float4 b0 = *(const float4*)(b + d0);
    float4 o0;
    o0.x = (a.x-mu)*inv*g0.x + b0.x; o0.y = (a.y-mu)*inv*g0.y + b0.y;
    o0.z = (a.z-mu)*inv*g0.z + b0.z; o0.w = (a.w-mu)*inv*g0.w + b0.w;
    store_hilo4(Ohi, Olo, rbase + d0, o0);

    float4 g1 = *(const float4*)(g + d1);
    float4 b1 = *(const float4*)(b + d1);
    float4 o1;
    o1.x = (c.x-mu)*inv*g1.x + b1.x; o1.y = (c.y-mu)*inv*g1.y + b1.y;
    o1.z = (c.z-mu)*inv*g1.z + b1.z; o1.w = (c.w-mu)*inv*g1.w + b1.w;
    store_hilo4(Ohi, Olo, rbase + d1, o1);
}

// ---------------- final layernorm on COMPACT cls buffer -> d_out (f32) ----------------
__global__ __launch_bounds__(128)
void lnf_c_kernel(const float* __restrict__ xc, const float* __restrict__ g,
                  const float* __restrict__ b, float* __restrict__ out)
{
    int row = blockIdx.x;
    int tid = threadIdx.x;
    const float* xp = xc + (size_t)row * DMODEL;
    float4 a = *(const float4*)(xp + tid*4);
    float4 c = *(const float4*)(xp + 512 + tid*4);
    float s  = a.x+a.y+a.z+a.w + c.x+c.y+c.z+c.w;
    float sq = a.x*a.x+a.y*a.y+a.z*a.z+a.w*a.w + c.x*c.x+c.y*c.y+c.z*c.z+c.w*c.w;
#pragma unroll
    for (int off = 16; off; off >>= 1) {
        s  += __shfl_xor_sync(0xffffffffu, s,  off);
        sq += __shfl_xor_sync(0xffffffffu, sq, off);
    }
    __shared__ float sm[8];
    int wid = tid >> 5, lane = tid & 31;
    if (lane == 0) { sm[wid] = s; sm[4+wid] = sq; }
    __syncthreads();
    s  = sm[0]+sm[1]+sm[2]+sm[3];
    sq = sm[4]+sm[5]+sm[6]+sm[7];
    float mu  = s * (1.f/DMODEL);
    float var = sq * (1.f/DMODEL) - mu*mu;
    float inv = rsqrtf(var + 1e-5f);

    int d0 = tid*4;
    float4 g0 = *(const float4*)(g + d0);
    float4 b0 = *(const float4*)(b + d0);
    float4 o0;
    o0.x = (a.x-mu)*inv*g0.x + b0.x; o0.y = (a.y-mu)*inv*g0.y + b0.y;
    o0.z = (a.z-mu)*inv*g0.z + b0.z; o0.w = (a.w-mu)*inv*g0.w + b0.w;
    *(float4*)(out + (size_t)row*DMODEL + d0) = o0;
    int d1 = 512 + tid*4;
    float4 g1 = *(const float4*)(g + d1);
    float4 b1 = *(const float4*)(b + d1);
    float4 o1;
    o1.x = (c.x-mu)*inv*g1.x + b1.x; o1.y = (c.y-mu)*inv*g1.y + b1.y;
    o1.z = (c.z-mu)*inv*g1.z + b1.z; o1.w = (c.w-mu)*inv*g1.w + b1.w;
    *(float4*)(out + (size_t)row*DMODEL + d1) = o1;
}

// ---------------- attention with fused RoPE: one block per (b,h) ----------------
#define ROPE_L2 0.83048202372184059f

__global__ __launch_bounds__(128)
void attn_kernel()
{
    __shared__ float KV[NTOK*HD];
    __shared__ float Ss[NTOK*67];

    int bh = blockIdx.x;
    int b = bh >> 4, h = bh & 15;
    int tid = threadIdx.x;
    size_t base = (size_t)b*NTOK*3*DMODEL + (size_t)h*HD;

    for (int idx = tid; idx < NTOK*32; idx += 128) {
        int n = idx >> 5, i = idx & 31;
        int ii = i & 15;
        int pos = (n == 0) ? 0 : ((i < 16) ? ((n-1) >> 3) : ((n-1) & 7));
        float ang = (float)pos * exp2f(-(float)ii * ROPE_L2);
        float cs = cosf(ang), sn = sinf(ang);
        float2 v = *(const float2*)(&g_qkv[base + (size_t)n*3*DMODEL + DMODEL + 2*i]);
        KV[n*HD + 2*i]   = v.x*cs - v.y*sn;
        KV[n*HD + 2*i+1] = v.y*cs + v.x*sn;
    }
    __syncthreads();

    int r = tid;
    float qreg[HD];
    if (r < NTOK) {
        const float* qp = &g_qkv[base + (size_t)r*3*DMODEL];
#pragma unroll
        for (int d4 = 0; d4 < 16; d4++) {
            float4 t4 = *(const float4*)(qp + d4*4);
            qreg[d4*4+0]=t4.x; qreg[d4*4+1]=t4.y; qreg[d4*4+2]=t4.z; qreg[d4*4+3]=t4.w;
        }
#pragma unroll
        for (int i = 0; i < 32; i++) {
            int ii = i & 15;
            int pos = (r == 0) ? 0 : ((i < 16) ? ((r-1) >> 3) : ((r-1) & 7));
            float ang = (float)pos * exp2f(-(float)ii * ROPE_L2);
            float cs = cosf(ang), sn = sinf(ang);
            float xe = qreg[2*i], xo = qreg[2*i+1];
            qreg[2*i]   = xe*cs - xo*sn;
            qreg[2*i+1] = xo*cs + xe*sn;
        }
#pragma unroll 1
        for (int j = 0; j < NTOK; j++) {
            float acc = 0.f;
#pragma unroll
            for (int d4 = 0; d4 < 16; d4++) {
                float4 kv = *(const float4*)(&KV[j*HD + d4*4]);
                acc += qreg[d4*4+0]*kv.x + qreg[d4*4+1]*kv.y
                     + qreg[d4*4+2]*kv.z + qreg[d4*4+3]*kv.w;
            }
            Ss[r*67 + j] = acc * 0.125f;
        }
        float m = -1e30f;
#pragma unroll 1
        for (int j = 0; j < NTOK; j++) m = fmaxf(m, Ss[r*67+j]);
        float sum = 0.f;
#pragma unroll 1
        for (int j = 0; j < NTOK; j++) {
            float e = expf(Ss[r*67+j] - m);
            Ss[r*67+j] = e;
            sum += e;
        }
        float invs = 1.0f / sum;
#pragma unroll 1
        for (int j = 0; j < NTOK; j++) Ss[r*67+j] *= invs;
    }
    __syncthreads();

    for (int idx = tid; idx < NTOK*HD; idx += 128) {
        int n = idx >> 6, d = idx & 63;
        KV[idx] = g_qkv[base + (size_t)n*3*DMODEL + 2*DMODEL + d];
    }
    __syncthreads();

    if (r < NTOK) {
        size_t obase = (size_t)(b*NTOK + r)*DMODEL + h*HD;
#pragma unroll 1
        for (int d4 = 0; d4 < 16; d4++) {
            float4 acc4 = make_float4(0.f,0.f,0.f,0.f);
#pragma unroll 5
            for (int j = 0; j < NTOK; j++) {
                float s = Ss[r*67 + j];
                float4 vv = *(const float4*)(&KV[j*HD + d4*4]);
                acc4.x += s*vv.x; acc4.y += s*vv.y;
                acc4.z += s*vv.z; acc4.w += s*vv.w;
            }
            store_hilo4(g_Ahi, g_Alo, obase + d4*4, acc4);
        }
    }
}

// ---------------- last-layer attention: only query row 0 per (b,h) ----------------
__global__ __launch_bounds__(128)
void attn_last_kernel()
{
    __shared__ float KV[NTOK*HD];
    __shared__ float Q[HD];
    __shared__ float P[NTOK];
    __shared__ float red[2];

    int bh = blockIdx.x;
    int b = bh >> 4, h = bh & 15;
    int tid = threadIdx.x;
    size_t base = (size_t)b*NTOK*3*DMODEL + (size_t)h*HD;

    if (h == 0) {
        for (int d = tid; d < DMODEL; d += 128)
            g_xp[(size_t)b*DMODEL + d] = g_x[(size_t)(b*NTOK)*DMODEL + d];
    }

    for (int idx = tid; idx < NTOK*32; idx += 128) {
        int n = idx >> 5, i = idx & 31;
        int ii = i & 15;
        int pos = (n == 0) ? 0 : ((i < 16) ? ((n-1) >> 3) : ((n-1) & 7));
        float ang = (float)pos * exp2f(-(float)ii * ROPE_L2);
        float cs = cosf(ang), sn = sinf(ang);
        float2 v = *(const float2*)(&g_qkv[base + (size_t)n*3*DMODEL + DMODEL + 2*i]);
        KV[n*HD + 2*i]   = v.x*cs - v.y*sn;
        KV[n*HD + 2*i+1] = v.y*cs + v.x*sn;
    }
    if (tid < HD) Q[tid] = g_qkv[base + tid];
    __syncthreads();

    if (tid < NTOK) {
        float acc = 0.f;
#pragma unroll
        for (int d = 0; d < HD; d++) acc += Q[d] * KV[tid*HD + d];
        P[tid] = acc * 0.125f;
    }
    __syncthreads();
    if (tid == 0) {
        float m = -1e30f;
        for (int j = 0; j < NTOK; j++) m = fmaxf(m, P[j]);
        red[0] = m;
    }
    __syncthreads();
    if (tid < NTOK) P[tid] = expf(P[tid] - red[0]);
    __syncthreads();
    if (tid == 0) {
        float s = 0.f;
        for (int j = 0; j < NTOK; j++) s += P[j];
        red[1] = 1.0f / s;
    }
    __syncthreads();
    if (tid < NTOK) P[tid] *= red[1];
    __syncthreads();

    for (int idx = tid; idx < NTOK*HD; idx += 128) {
        int n = idx >> 6, d = idx & 63;
        KV[idx] = g_qkv[base + (size_t)n*3*DMODEL + 2*DMODEL + d];
    }
    __syncthreads();

    if (tid < HD) {
        float acc = 0.f;
#pragma unroll 1
        for (int j = 0; j < NTOK; j++) acc += P[j] * KV[j*HD + tid];
        store_hilo1(g_Ahi, g_Alo, (size_t)b*DMODEL + h*HD + tid, acc);
    }
}

// ---------------- launch ----------------
extern "C" void kernel_launch(void* const* d_in, const int* in_sizes, int n_in,
                              void* d_out, int out_size)
{
    const float* img     = (const float*)d_in[0];
    const float* patch_W = (const float*)d_in[1];
    const float* patch_b = (const float*)d_in[2];
    const float* cls     = (const float*)d_in[3];
    const float* ln1_g   = (const float*)d_in[4];
    const float* ln1_b   = (const float*)d_in[5];
    const float* Wqkv    = (const float*)d_in[6];
    const float* Wproj   = (const float*)d_in[7];
    const float* bproj   = (const float*)d_in[8];
    const float* ln2_g   = (const float*)d_in[9];
    const float* ln2_b   = (const float*)d_in[10];
    const float* W1      = (const float*)d_in[11];
    const float* b1      = (const float*)d_in[12];
    const float* W2      = (const float*)d_in[13];
    const float* b2      = (const float*)d_in[14];
    const float* lnf_g   = (const float*)d_in[15];
    const float* lnf_b   = (const float*)d_in[16];
    float* out = (float*)d_out;

    cudaFuncSetAttribute(gemm_mma, cudaFuncAttributeMaxDynamicSharedMemorySize, GEMM_SMEM);

    float *x, *qkv, *xp, *part;
    __nv_bfloat16 *Ahi, *Alo, *Mhi, *Mlo, *Bh, *Bl;
    __nv_bfloat16 *Wqh, *Wql, *Wph, *Wpl, *W1h, *W1l, *W2h, *W2l;
    cudaGetSymbolAddress((void**)&x,    g_x);
    cudaGetSymbolAddress((void**)&qkv,  g_qkv);
    cudaGetSymbolAddress((void**)&xp,   g_xp);
    cudaGetSymbolAddress((void**)&part, g_part);
    cudaGetSymbolAddress((void**)&Ahi,  g_Ahi);
    cudaGetSymbolAddress((void**)&Alo,  g_Alo);
    cudaGetSymbolAddress((void**)&Mhi,  g_Mhi);
    cudaGetSymbolAddress((void**)&Mlo,  g_Mlo);
    cudaGetSymbolAddress((void**)&Bh,   g_Bhi);
    cudaGetSymbolAddress((void**)&Bl,   g_Blo);
    cudaGetSymbolAddress((void**)&Wqh,  g_Wqh);
    cudaGetSymbolAddress((void**)&Wql,  g_Wql);
    cudaGetSymbolAddress((void**)&Wph,  g_Wph);
    cudaGetSymbolAddress((void**)&Wpl,  g_Wpl);
    cudaGetSymbolAddress((void**)&W1h,  g_W1h);
    cudaGetSymbolAddress((void**)&W1l,  g_W1l);
    cudaGetSymbolAddress((void**)&W2h,  g_W2h);
    cudaGetSymbolAddress((void**)&W2l,  g_W2l);

    float* xc  = xp;                    // 256x1024 compact cls residual
    float* xc2 = xp + 256*DMODEL;       // 256x1024 compact working buffer

    // ---- side stream: all weight conversions, forked from the main stream ----
    cudaStream_t s2;
    cudaStreamCreateWithFlags(&s2, cudaStreamNonBlocking);
    cudaEvent_t evFork, evPatch, evW[DEPTH];
    cudaEventCreateWithFlags(&evFork, cudaEventDisableTiming);
    cudaEventCreateWithFlags(&evPatch, cudaEventDisableTiming);
    for (int l = 0; l < DEPTH; l++)
        cudaEventCreateWithFlags(&evW[l], cudaEventDisableTiming);

    cudaEventRecord(evFork, 0);
    cudaStreamWaitEvent(s2, evFork, 0);

    wconv_kernel<<<dim3(DMODEL/32, 1024/32), dim3(32,8), 0, s2>>>(patch_W, Bh, Bl, 1024, DMODEL);
    cudaEventRecord(evPatch, s2);

    for (int l = 0; l < DEPTH; l++) {
        const float* wq = Wqkv  + (size_t)l*DMODEL*3*DMODEL;
        const float* wp = Wproj + (size_t)l*DMODEL*DMODEL;
        const float* w1 = W1    + (size_t)l*DMODEL*FF;
        const float* w2 = W2    + (size_t)l*FF*DMODEL;
        wconv_kernel<<<dim3(3*DMODEL/32, DMODEL/32), dim3(32,8), 0, s2>>>(
            wq, Wqh + (size_t)l*DMODEL*3*DMODEL, Wql + (size_t)l*DMODEL*3*DMODEL, DMODEL, 3*DMODEL);
        wconv_kernel<<<dim3(DMODEL/32, DMODEL/32), dim3(32,8), 0, s2>>>(
            wp, Wph + (size_t)l*DMODEL*DMODEL, Wpl + (size_t)l*DMODEL*DMODEL, DMODEL, DMODEL);
        wconv_kernel<<<dim3(FF/32, DMODEL/32), dim3(32,8), 0, s2>>>(
            w1, W1h + (size_t)l*DMODEL*FF, W1l + (size_t)l*DMODEL*FF, DMODEL, FF);
        wconv_kernel<<<dim3(DMODEL/32, FF/32), dim3(32,8), 0, s2>>>(
            w2, W2h + (size_t)l*FF*DMODEL, W2l + (size_t)l*FF*DMODEL, FF, DMODEL);
        cudaEventRecord(evW[l], s2);
    }

    // ---- main stream: patch embedding ----
    {
        int total = MPATCH * PSZ * PSZ;
        gather_kernel<<<(total+255)/256, 256>>>(img);
        cudaStreamWaitEvent(0, evPatch, 0);
        gemm_mma<<<dim3(DMODEL/128, MPATCH/128), 256, GEMM_SMEM>>>(
            Mhi, Mlo, Bh, Bl, patch_b, nullptr, xp, nullptr, nullptr,
            MPATCH, DMODEL, 1024, 1024, 1);
        int tot2 = BN_TOK*DMODEL;
        assemble_kernel<<<(tot2+255)/256, 256>>>(cls);
    }

    // ---- layers 0..10 (full); mlp2 is split-K=2, reduced in next layer's ln1 ----
    for (int l = 0; l < DEPTH-1; l++) {
        const __nv_bfloat16* wqh = Wqh + (size_t)l*DMODEL*3*DMODEL;
        const __nv_bfloat16* wql = Wql + (size_t)l*DMODEL*3*DMODEL;
        const __nv_bfloat16* wph = Wph + (size_t)l*DMODEL*DMODEL;
        const __nv_bfloat16* wpl = Wpl + (size_t)l*DMODEL*DMODEL;
        const __nv_bfloat16* w1h = W1h + (size_t)l*DMODEL*FF;
        const __nv_bfloat16* w1l = W1l + (size_t)l*DMODEL*FF;
        const __nv_bfloat16* w2h = W2h + (size_t)l*FF*DMODEL;
        const __nv_bfloat16* w2l = W2l + (size_t)l*FF*DMODEL;

        // ln1: layer 0 plain; layers >=1 fused with previous layer's mlp2 reduce
        if (l == 0) {
            ln_kernel<<<BN_TOK, 128>>>(x, ln1_g + l*DMODEL, ln1_b + l*DMODEL, Ahi, Alo);
        } else {
            ln_red_kernel<<<BN_TOK, 128>>>(x, part, b2 + (l-1)*DMODEL,
                                           ln1_g + l*DMODEL, ln1_b + l*DMODEL, Ahi, Alo);
        }

        cudaStreamWaitEvent(0, evW[l], 0);
        gemm_mma<<<dim3(3*DMODEL/128, BN_TOK/128), 256, GEMM_SMEM>>>(
            Ahi, Alo, wqh, wql, nullptr, nullptr, qkv, nullptr, nullptr,
            BN_TOK, 3*DMODEL, DMODEL, DMODEL, 0);

        attn_kernel<<<BATCH*HEADS, 128>>>();

        gemm_mma<<<dim3(DMODEL/128, BN_TOK/128), 256, GEMM_SMEM>>>(
            Ahi, Alo, wph, wpl, bproj + l*DMODEL, x, x, nullptr, nullptr,
            BN_TOK, DMODEL, DMODEL, DMODEL, 2);

        ln_kernel<<<BN_TOK, 128>>>(x, ln2_g + l*DMODEL, ln2_b + l*DMODEL, Ahi, Alo);

        gemm_mma<<<dim3(FF/128, BN_TOK/128), 256, GEMM_SMEM>>>(
            Ahi, Alo, w1h, w1l, b1 + l*FF, nullptr, nullptr, Mhi, Mlo,
            BN_TOK, FF, DMODEL, DMODEL, 3);

        // mlp2: split-K=2 in one launch; partials -> g_part
        gemm_mma<<<dim3(DMODEL/128, BN_TOK/128, 2), 256, GEMM_SMEM>>>(
            Mhi, Mlo, w2h, w2l, nullptr, nullptr, part, nullptr, nullptr,
            BN_TOK, DMODEL, FF/2, FF, 4);
    }

    // ---- layer 11 (only cls rows survive) ----
    {
        const int l = DEPTH-1;
        const __nv_bfloat16* wqh = Wqh + (size_t)l*DMODEL*3*DMODEL;
        const __nv_bfloat16* wql = Wql + (size_t)l*DMODEL*3*DMODEL;
        const __nv_bfloat16* wph = Wph + (size_t)l*DMODEL*DMODEL;
        const __nv_bfloat16* wpl = Wpl + (size_t)l*DMODEL*DMODEL;
        const __nv_bfloat16* w1h = W1h + (size_t)l*DMODEL*FF;
        const __nv_bfloat16* w1l = W1l + (size_t)l*DMODEL*FF;
        const __nv_bfloat16* w2h = W2h + (size_t)l*FF*DMODEL;
        const __nv_bfloat16* w2l = W2l + (size_t)l*FF*DMODEL;

        // ln1 fused with layer 10's mlp2 reduce
        ln_red_kernel<<<BN_TOK, 128>>>(x, part, b2 + (l-1)*DMODEL,
                                       ln1_g + l*DMODEL, ln1_b + l*DMODEL, Ahi, Alo);

        cudaStreamWaitEvent(0, evW[l], 0);
        gemm_mma<<<dim3(3*DMODEL/128, BN_TOK/128), 256, GEMM_SMEM>>>(
            Ahi, Alo, wqh, wql, nullptr, nullptr, qkv, nullptr, nullptr,
            BN_TOK, 3*DMODEL, DMODEL, DMODEL, 0);

        attn_last_kernel<<<BATCH*HEADS, 128>>>();   // also fills xc (cls rows)

        gemm_mma<<<dim3(DMODEL/128, 2), 256, GEMM_SMEM>>>(
            Ahi, Alo, wph, wpl, bproj + l*DMODEL, xc, xc2, nullptr, nullptr,
            256, DMODEL, DMODEL, DMODEL, 2);

        ln_kernel<<<256, 128>>>(xc2, ln2_g + l*DMODEL, ln2_b + l*DMODEL, Ahi, Alo);

        gemm_mma<<<dim3(FF/128, 2), 256, GEMM_SMEM>>>(
            Ahi, Alo, w1h, w1l, b1 + l*FF, nullptr, nullptr, Mhi, Mlo,
            256, FF, DMODEL, DMODEL, 3);

        gemm_mma<<<dim3(DMODEL/128, 2), 256, GEMM_SMEM>>>(
            Mhi, Mlo, w2h, w2l, b2 + l*DMODEL, xc2, xc2, nullptr, nullptr,
            256, DMODEL, FF, FF, 2);

        lnf_c_kernel<<<BATCH, 128>>>(xc2, lnf_g, lnf_b, out);
    }
}

// round 15
// speedup vs baseline: 1.0429x; 1.0429x over previous
#include <cuda_runtime.h>
#include <cuda_bf16.h>
#include <math.h>
#include <cstdint>

// ---------------- problem constants ----------------
#define BATCH   256
#define NTOK    65
#define BN_TOK  (BATCH*NTOK)      // 16640
#define DMODEL  1024
#define HEADS   16
#define HD      64
#define FF      4096
#define DEPTH   12
#define NPATCH  64
#define PSZ     32
#define IMGSZ   256
#define MPATCH  (BATCH*NPATCH)    // 16384

// ---------------- scratch ----------------
__device__ __align__(16) float g_x   [BN_TOK*DMODEL];
__device__ __align__(16) float g_qkv [BN_TOK*3*DMODEL];
__device__ __align__(16) float g_xp  [MPATCH*DMODEL];   // xc / xc2 compact buffers
__device__ __align__(16) __nv_bfloat16 g_Ahi[BN_TOK*DMODEL];
__device__ __align__(16) __nv_bfloat16 g_Alo[BN_TOK*DMODEL];
__device__ __align__(16) __nv_bfloat16 g_Mhi[BN_TOK*FF];
__device__ __align__(16) __nv_bfloat16 g_Mlo[BN_TOK*FF];
__device__ __align__(16) __nv_bfloat16 g_Bhi[DMODEL*DMODEL];   // patch weights only
__device__ __align__(16) __nv_bfloat16 g_Blo[DMODEL*DMODEL];

// per-layer pre-converted weights (side-stream targets)
__device__ __align__(16) __nv_bfloat16 g_Wqh[DEPTH*DMODEL*3*DMODEL];
__device__ __align__(16) __nv_bfloat16 g_Wql[DEPTH*DMODEL*3*DMODEL];
__device__ __align__(16) __nv_bfloat16 g_Wph[DEPTH*DMODEL*DMODEL];
__device__ __align__(16) __nv_bfloat16 g_Wpl[DEPTH*DMODEL*DMODEL];
__device__ __align__(16) __nv_bfloat16 g_W1h[DEPTH*DMODEL*FF];
__device__ __align__(16) __nv_bfloat16 g_W1l[DEPTH*DMODEL*FF];
__device__ __align__(16) __nv_bfloat16 g_W2h[DEPTH*FF*DMODEL];
__device__ __align__(16) __nv_bfloat16 g_W2l[DEPTH*FF*DMODEL];

// ---------------- PTX helpers (base-target sm_80+ only) ----------------
__device__ __forceinline__ uint32_t smem_u32(const void* p) {
    uint32_t a;
    asm("{ .reg .u64 t; cvta.to.shared.u64 t, %1; cvt.u32.u64 %0, t; }" : "=r"(a) : "l"(p));
    return a;
}
__device__ __forceinline__ void cpasync16(uint32_t dst, const void* src) {
    asm volatile("cp.async.cg.shared.global [%0], [%1], 16;" :: "r"(dst), "l"(src));
}
__device__ __forceinline__ void cpasync_commit() {
    asm volatile("cp.async.commit_group;" ::: "memory");
}
__device__ __forceinline__ void cpasync_wait0() {
    asm volatile("cp.async.wait_group 0;" ::: "memory");
}
__device__ __forceinline__ void cpasync_wait1() {
    asm volatile("cp.async.wait_group 1;" ::: "memory");
}
__device__ __forceinline__ void ldsm4(uint32_t* r, uint32_t addr) {
    asm volatile("ldmatrix.sync.aligned.m8n8.x4.shared.b16 {%0,%1,%2,%3}, [%4];"
                 : "=r"(r[0]), "=r"(r[1]), "=r"(r[2]), "=r"(r[3]) : "r"(addr));
}
__device__ __forceinline__ void mma16816(float* c, const uint32_t* a, const uint32_t* b) {
    asm volatile("mma.sync.aligned.m16n8k16.row.col.f32.bf16.bf16.f32 "
                 "{%0,%1,%2,%3}, {%4,%5,%6,%7}, {%8,%9}, {%0,%1,%2,%3};"
                 : "+f"(c[0]), "+f"(c[1]), "+f"(c[2]), "+f"(c[3])
                 : "r"(a[0]), "r"(a[1]), "r"(a[2]), "r"(a[3]), "r"(b[0]), "r"(b[1]));
}

// ---------------- small helpers ----------------
__device__ __forceinline__ float gelu_f(float v) {
    return 0.5f * v * (1.0f + erff(v * 0.70710678118654752440f));
}
__device__ __forceinline__ void store_hilo4(__nv_bfloat16* Hi, __nv_bfloat16* Lo, size_t idx, float4 v) {
    __nv_bfloat162 h0 = __floats2bfloat162_rn(v.x, v.y);
    __nv_bfloat162 h1 = __floats2bfloat162_rn(v.z, v.w);
    __nv_bfloat162 l0 = __floats2bfloat162_rn(v.x - __low2float(h0), v.y - __high2float(h0));
    __nv_bfloat162 l1 = __floats2bfloat162_rn(v.z - __low2float(h1), v.w - __high2float(h1));
    *reinterpret_cast<__nv_bfloat162*>(Hi + idx)     = h0;
    *reinterpret_cast<__nv_bfloat162*>(Hi + idx + 2) = h1;
    *reinterpret_cast<__nv_bfloat162*>(Lo + idx)     = l0;
    *reinterpret_cast<__nv_bfloat162*>(Lo + idx + 2) = l1;
}
__device__ __forceinline__ void store_hilo2(__nv_bfloat16* Hi, __nv_bfloat16* Lo, size_t idx, float v0, float v1) {
    __nv_bfloat162 h = __floats2bfloat162_rn(v0, v1);
    __nv_bfloat162 l = __floats2bfloat162_rn(v0 - __low2float(h), v1 - __high2float(h));
    *reinterpret_cast<__nv_bfloat162*>(Hi + idx) = h;
    *reinterpret_cast<__nv_bfloat162*>(Lo + idx) = l;
}
__device__ __forceinline__ void store_hilo1(__nv_bfloat16* Hi, __nv_bfloat16* Lo, size_t idx, float v) {
    __nv_bfloat16 h = __float2bfloat16(v);
    Hi[idx] = h;
    Lo[idx] = __float2bfloat16(v - __bfloat162float(h));
}

// ---------------- patch gather -> bf16 hi/lo rows [16384, 1024] ----------------
__global__ void gather_kernel(const float* __restrict__ img) {
    int idx = blockIdx.x * blockDim.x + threadIdx.x;
    const int total = MPATCH * PSZ * PSZ;
    if (idx >= total) return;
    int k = idx & 1023;
    int p = (idx >> 10) & 63;
    int b = idx >> 16;
    int i = k >> 5, j = k & 31;
    int gr = p >> 3, gc = p & 7;
    float v = img[(size_t)b*IMGSZ*IMGSZ + (size_t)(gr*PSZ + i)*IMGSZ + gc*PSZ + j];
    __nv_bfloat16 h = __float2bfloat16(v);
    g_Mhi[idx] = h;
    g_Mlo[idx] = __float2bfloat16(v - __bfloat162float(h));
}

// ---------------- write cls token rows of x (patch rows come from GEMM epi=5) ----------------
__global__ void assemble_cls_kernel(const float* __restrict__ cls) {
    int idx = blockIdx.x * blockDim.x + threadIdx.x;
    if (idx >= BATCH*DMODEL) return;
    int b = idx >> 10, d = idx & 1023;
    g_x[(size_t)(b*NTOK)*DMODEL + d] = cls[d];
}

// ---------------- weight transpose-convert: W[K,N] -> Bt[N,K] hi/lo bf16 ----------------
__global__ __launch_bounds__(256)
void wconv_kernel(const float* __restrict__ W, __nv_bfloat16* __restrict__ Bh,
                  __nv_bfloat16* __restrict__ Bl, int K, int N) {
    __shared__ float t[32][33];
    int n0 = blockIdx.x * 32, k0 = blockIdx.y * 32;
    int tx = threadIdx.x, ty = threadIdx.y;   // 32 x 8
#pragma unroll
    for (int i = 0; i < 32; i += 8)
        t[ty+i][tx] = W[(size_t)(k0+ty+i)*N + n0+tx];
    __syncthreads();
#pragma unroll
    for (int i = 0; i < 32; i += 8) {
        int n = ty + i;
        float v = t[tx][n];
        __nv_bfloat16 h = __float2bfloat16(v);
        size_t o = (size_t)(n0+n)*K + k0+tx;
        Bh[o] = h;
        Bl[o] = __float2bfloat16(v - __bfloat162float(h));
    }
}

// ---------------- mma.sync GEMM 128x128 (3xBF16 compensation) ----------------
// epi: 0 plain f32, 1 +bias, 2 +bias+residual, 3 +bias+gelu->hi/lo,
//      5 +bias with row remap row -> (row>>6)*65 + (row&63) + 1 (patch scatter).
#define TILEB  (128*64)                  // 8192 bytes per tile
#define STAGEB (4*TILEB)                 // 32768
#define NSTAGE 3
#define GEMM_SMEM (NSTAGE*STAGEB)        // 98304

__device__ __forceinline__ void load_stage(uint32_t sbase,
    const __nv_bfloat16* __restrict__ Ahi, const __nv_bfloat16* __restrict__ Alo,
    const __nv_bfloat16* __restrict__ Bhi, const __nv_bfloat16* __restrict__ Blo,
    int row0, int col0, int K, int k0, int tid)
{
#pragma unroll
    for (int i = 0; i < 2; i++) {
        int c   = tid + i*256;
        int row = c >> 2, lc = c & 3;
        uint32_t soff = (uint32_t)(row*64 + ((lc ^ ((row>>1)&3))*16));
        size_t ga = (size_t)(row0 + row)*K + k0 + lc*8;
        size_t gb = (size_t)(col0 + row)*K + k0 + lc*8;
        cpasync16(sbase +            soff, Ahi + ga);
        cpasync16(sbase +   TILEB +  soff, Alo + ga);
        cpasync16(sbase + 2*TILEB +  soff, Bhi + gb);
        cpasync16(sbase + 3*TILEB +  soff, Blo + gb);
    }
    cpasync_commit();
}

__global__ __launch_bounds__(256, 2)
void gemm_mma(const __nv_bfloat16* __restrict__ Ahi, const __nv_bfloat16* __restrict__ Alo,
              const __nv_bfloat16* __restrict__ Bhi, const __nv_bfloat16* __restrict__ Blo,
              const float* __restrict__ bias, const float* __restrict__ res,
              float* __restrict__ C, __nv_bfloat16* __restrict__ Ohi, __nv_bfloat16* __restrict__ Olo,
              int M, int Nn, int K, int epi)
{
    extern __shared__ char smem[];
    uint32_t sb = smem_u32(smem);
    int tid = threadIdx.x;
    int wid = tid >> 5, lane = tid & 31;
    int row0 = blockIdx.y * 128, col0 = blockIdx.x * 128;

    int wm = (wid & 1) * 64;
    int wn = (wid >> 1) * 32;

    int aRow = wm + (lane & 15);
    uint32_t aSw  = (uint32_t)(((aRow >> 1) & 3) << 4);
    uint32_t aKB  = (uint32_t)(((lane >> 4) & 1) << 4);
    uint32_t aBase = (uint32_t)(aRow * 64);
    int bRow = wn + (lane & 7) + ((lane >> 4) & 1) * 8;
    uint32_t bSw  = (uint32_t)(((bRow >> 1) & 3) << 4);
    uint32_t bKB  = (uint32_t)(((lane >> 3) & 1) << 4);
    uint32_t bBase = (uint32_t)(bRow * 64);

    float acc[4][4][4];
#pragma unroll
    for (int mt = 0; mt < 4; mt++)
#pragma unroll
        for (int nt = 0; nt < 4; nt++)
#pragma unroll
            for (int e = 0; e < 4; e++) acc[mt][nt][e] = 0.f;

    int NC = K >> 5;
    load_stage(sb, Ahi, Alo, Bhi, Blo, row0, col0, K, 0, tid);
    if (NC > 1)
        load_stage(sb + STAGEB, Ahi, Alo, Bhi, Blo, row0, col0, K, 32, tid);

    uint32_t stOff = 0;
    uint32_t ldOff = (NC > 1) ? 2u*STAGEB : STAGEB;

#pragma unroll 1
    for (int kc = 0; kc < NC; kc++) {
        if (kc + 1 < NC) cpasync_wait1(); else cpasync_wait0();
        __syncthreads();
        if (kc + 2 < NC) {
            load_stage(sb + ldOff, Ahi, Alo, Bhi, Blo, row0, col0, K, (kc + 2) << 5, tid);
        }
        uint32_t st = sb + stOff;
        stOff += STAGEB; if (stOff == NSTAGE*STAGEB) stOff = 0;
        ldOff += STAGEB; if (ldOff == NSTAGE*STAGEB) ldOff = 0;

#pragma unroll
        for (int ks2 = 0; ks2 < 2; ks2++) {
            uint32_t kadd = (uint32_t)ks2 * 32;
            uint32_t aLK = (kadd + aKB) ^ aSw;
            uint32_t bLK = (kadd + bKB) ^ bSw;
            uint32_t ah[4][4], bh[2][4], al[4][4], bl[2][4];
#pragma unroll
            for (int mt = 0; mt < 4; mt++)
                ldsm4(ah[mt], st + aBase + (uint32_t)mt*1024 + aLK);
#pragma unroll
            for (int ntp = 0; ntp < 2; ntp++)
                ldsm4(bh[ntp], st + 2*TILEB + bBase + (uint32_t)ntp*1024 + bLK);
#pragma unroll
            for (int mt = 0; mt < 4; mt++)
                ldsm4(al[mt], st + TILEB + aBase + (uint32_t)mt*1024 + aLK);
            // hi x hi
#pragma unroll
            for (int mt = 0; mt < 4; mt++)
#pragma unroll
                for (int nt = 0; nt < 4; nt++)
                    mma16816(acc[mt][nt], ah[mt], &bh[nt>>1][(nt&1)*2]);
#pragma unroll
            for (int ntp = 0; ntp < 2; ntp++)
                ldsm4(bl[ntp], st + 3*TILEB + bBase + (uint32_t)ntp*1024 + bLK);
            // lo x hi
#pragma unroll
            for (int mt = 0; mt < 4; mt++)
#pragma unroll
                for (int nt = 0; nt < 4; nt++)
                    mma16816(acc[mt][nt], al[mt], &bh[nt>>1][(nt&1)*2]);
            // hi x lo
#pragma unroll
            for (int mt = 0; mt < 4; mt++)
#pragma unroll
                for (int nt = 0; nt < 4; nt++)
                    mma16816(acc[mt][nt], ah[mt], &bl[nt>>1][(nt&1)*2]);
        }
    }

    // ---------------- epilogue ----------------
    int base_r = row0 + wm;
    int base_c = col0 + wn;
#pragma unroll
    for (int mt = 0; mt < 4; mt++) {
#pragma unroll
        for (int nt = 0; nt < 4; nt++) {
            int r = base_r + mt*16 + (lane >> 2);
            int c = base_c + nt*8 + (lane & 3)*2;
            float* a4 = acc[mt][nt];
#pragma unroll
            for (int half = 0; half < 2; half++) {
                int rr = r + half*8;
                float v0 = a4[half*2], v1 = a4[half*2+1];
                size_t off = (size_t)rr * Nn + c;
                if (epi == 5) off = (size_t)((rr >> 6)*NTOK + (rr & 63) + 1) * Nn + c;
                if (epi != 0) {
                    float2 bb = *reinterpret_cast<const float2*>(bias + c);
                    v0 += bb.x; v1 += bb.y;
                }
                if (epi == 3) {
                    v0 = gelu_f(v0); v1 = gelu_f(v1);
                    store_hilo2(Ohi, Olo, off, v0, v1);
                } else {
                    if (epi == 2) {
                        float2 rr2 = *reinterpret_cast<const float2*>(res + off);
                        v0 += rr2.x; v1 += rr2.y;
                    }
                    float2 o; o.x = v0; o.y = v1;
                    *reinterpret_cast<float2*>(C + off) = o;
                }
            }
        }
    }
}

// ---------------- layernorm -> bf16 hi/lo ----------------
__global__ __launch_bounds__(128)
void ln_kernel(const float* __restrict__ x, const float* __restrict__ g,
               const float* __restrict__ b, __nv_bfloat16* __restrict__ Ohi,
               __nv_bfloat16* __restrict__ Olo)
{
    int row = blockIdx.x;
    int tid = threadIdx.x;
    const float* xp = x + (size_t)row * DMODEL;
    float4 a = *(const float4*)(xp + tid*4);
    float4 c = *(const float4*)(xp + 512 + tid*4);
    float s  = a.x+a.y+a.z+a.w + c.x+c.y+c.z+c.w;
    float sq = a.x*a.x+a.y*a.y+a.z*a.z+a.w*a.w + c.x*c.x+c.y*c.y+c.z*c.z+c.w*c.w;
#pragma unroll
    for (int off = 16; off; off >>= 1) {
        s  += __shfl_xor_sync(0xffffffffu, s,  off);
        sq += __shfl_xor_sync(0xffffffffu, sq, off);
    }
    __shared__ float sm[8];
    int wid = tid >> 5, lane = tid & 31;
    if (lane == 0) { sm[wid] = s; sm[4+wid] = sq; }
    __syncthreads();
    s  = sm[0]+sm[1]+sm[2]+sm[3];
    sq = sm[4]+sm[5]+sm[6]+sm[7];
    float mu  = s * (1.f/DMODEL);
    float var = sq * (1.f/DMODEL) - mu*mu;
    float inv = rsqrtf(var + 1e-5f);

    int d0 = tid*4;
    float4 g0 = *(const float4*)(g + d0);
    float4 b0 = *(const float4*)(b + d0);
    float4 o0;
    o0.x = (a.x-mu)*inv*g0.x + b0.x; o0.y = (a.y-mu)*inv*g0.y + b0.y;
    o0.z = (a.z-mu)*inv*g0.z + b0.z; o0.w = (a.w-mu)*inv*g0.w + b0.w;
    store_hilo4(Ohi, Olo, (size_t)row*DMODEL + d0, o0);

    int d1 = 512 + tid*4;
    float4 g1 = *(const float4*)(g + d1);
    float4 b1 = *(const float4*)(b + d1);
    float4 o1;
    o1.x = (c.x-mu)*inv*g1.x + b1.x; o1.y = (c.y-mu)*inv*g1.y + b1.y;
    o1.z = (c.z-mu)*inv*g1.z + b1.z; o1.w = (c.w-mu)*inv*g1.w + b1.w;
    store_hilo4(Ohi, Olo, (size_t)row*DMODEL + d1, o1);
}

// ---------------- final layernorm on COMPACT cls buffer -> d_out (f32) ----------------
__global__ __launch_bounds__(128)
void lnf_c_kernel(const float* __restrict__ xc, const float* __restrict__ g,
                  const float* __restrict__ b, float* __restrict__ out)
{
    int row = blockIdx.x;
    int tid = threadIdx.x;
    const float* xp = xc + (size_t)row * DMODEL;
    float4 a = *(const float4*)(xp + tid*4);
    float4 c = *(const float4*)(xp + 512 + tid*4);
    float s  = a.x+a.y+a.z+a.w + c.x+c.y+c.z+c.w;
    float sq = a.x*a.x+a.y*a.y+a.z*a.z+a.w*a.w + c.x*c.x+c.y*c.y+c.z*c.z+c.w*c.w;
#pragma unroll
    for (int off = 16; off; off >>= 1) {
        s  += __shfl_xor_sync(0xffffffffu, s,  off);
        sq += __shfl_xor_sync(0xffffffffu, sq, off);
    }
    __shared__ float sm[8];
    int wid = tid >> 5, lane = tid & 31;
    if (lane == 0) { sm[wid] = s; sm[4+wid] = sq; }
    __syncthreads();
    s  = sm[0]+sm[1]+sm[2]+sm[3];
    sq = sm[4]+sm[5]+sm[6]+sm[7];
    float mu  = s * (1.f/DMODEL);
    float var = sq * (1.f/DMODEL) - mu*mu;
    float inv = rsqrtf(var + 1e-5f);

    int d0 = tid*4;
    float4 g0 = *(const float4*)(g + d0);
    float4 b0 = *(const float4*)(b + d0);
    float4 o0;
    o0.x = (a.x-mu)*inv*g0.x + b0.x; o0.y = (a.y-mu)*inv*g0.y + b0.y;
    o0.z = (a.z-mu)*inv*g0.z + b0.z; o0.w = (a.w-mu)*inv*g0.w + b0.w;
    *(float4*)(out + (size_t)row*DMODEL + d0) = o0;
    int d1 = 512 + tid*4;
    float4 g1 = *(const float4*)(g + d1);
    float4 b1 = *(const float4*)(b + d1);
    float4 o1;
    o1.x = (c.x-mu)*inv*g1.x + b1.x; o1.y = (c.y-mu)*inv*g1.y + b1.y;
    o1.z = (c.z-mu)*inv*g1.z + b1.z; o1.w = (c.w-mu)*inv*g1.w + b1.w;
    *(float4*)(out + (size_t)row*DMODEL + d1) = o1;
}

// ---------------- attention with fused RoPE: one block per (b,h) ----------------
#define ROPE_L2 0.83048202372184059f

__global__ __launch_bounds__(128)
void attn_kernel()
{
    __shared__ float KV[NTOK*HD];
    __shared__ float Ss[NTOK*67];

    int bh = blockIdx.x;
    int b = bh >> 4, h = bh & 15;
    int tid = threadIdx.x;
    size_t base = (size_t)b*NTOK*3*DMODEL + (size_t)h*HD;

    for (int idx = tid; idx < NTOK*32; idx += 128) {
        int n = idx >> 5, i = idx & 31;
        int ii = i & 15;
        int pos = (n == 0) ? 0 : ((i < 16) ? ((n-1) >> 3) : ((n-1) & 7));
        float ang = (float)pos * exp2f(-(float)ii * ROPE_L2);
        float cs = cosf(ang), sn = sinf(ang);
        float2 v = *(const float2*)(&g_qkv[base + (size_t)n*3*DMODEL + DMODEL + 2*i]);
        KV[n*HD + 2*i]   = v.x*cs - v.y*sn;
        KV[n*HD + 2*i+1] = v.y*cs + v.x*sn;
    }
    __syncthreads();

    int r = tid;
    float qreg[HD];
    if (r < NTOK) {
        const float* qp = &g_qkv[base + (size_t)r*3*DMODEL];
#pragma unroll
        for (int d4 = 0; d4 < 16; d4++) {
            float4 t4 = *(const float4*)(qp + d4*4);
            qreg[d4*4+0]=t4.x; qreg[d4*4+1]=t4.y; qreg[d4*4+2]=t4.z; qreg[d4*4+3]=t4.w;
        }
#pragma unroll
        for (int i = 0; i < 32; i++) {
            int ii = i & 15;
            int pos = (r == 0) ? 0 : ((i < 16) ? ((r-1) >> 3) : ((r-1) & 7));
            float ang = (float)pos * exp2f(-(float)ii * ROPE_L2);
            float cs = cosf(ang), sn = sinf(ang);
            float xe = qreg[2*i], xo = qreg[2*i+1];
            qreg[2*i]   = xe*cs - xo*sn;
            qreg[2*i+1] = xo*cs + xe*sn;
        }
#pragma unroll 1
        for (int j = 0; j < NTOK; j++) {
            float acc = 0.f;
#pragma unroll
            for (int d4 = 0; d4 < 16; d4++) {
                float4 kv = *(const float4*)(&KV[j*HD + d4*4]);
                acc += qreg[d4*4+0]*kv.x + qreg[d4*4+1]*kv.y
                     + qreg[d4*4+2]*kv.z + qreg[d4*4+3]*kv.w;
            }
            Ss[r*67 + j] = acc * 0.125f;
        }
        float m = -1e30f;
#pragma unroll 1
        for (int j = 0; j < NTOK; j++) m = fmaxf(m, Ss[r*67+j]);
        float sum = 0.f;
#pragma unroll 1
        for (int j = 0; j < NTOK; j++) {
            float e = expf(Ss[r*67+j] - m);
            Ss[r*67+j] = e;
            sum += e;
        }
        float invs = 1.0f / sum;
#pragma unroll 1
        for (int j = 0; j < NTOK; j++) Ss[r*67+j] *= invs;
    }
    __syncthreads();

    for (int idx = tid; idx < NTOK*HD; idx += 128) {
        int n = idx >> 6, d = idx & 63;
        KV[idx] = g_qkv[base + (size_t)n*3*DMODEL + 2*DMODEL + d];
    }
    __syncthreads();

    if (r < NTOK) {
        size_t obase = (size_t)(b*NTOK + r)*DMODEL + h*HD;
#pragma unroll 1
        for (int d4 = 0; d4 < 16; d4++) {
            float4 acc4 = make_float4(0.f,0.f,0.f,0.f);
#pragma unroll 5
            for (int j = 0; j < NTOK; j++) {
                float s = Ss[r*67 + j];
                float4 vv = *(const float4*)(&KV[j*HD + d4*4]);
                acc4.x += s*vv.x; acc4.y += s*vv.y;
                acc4.z += s*vv.z; acc4.w += s*vv.w;
            }
            store_hilo4(g_Ahi, g_Alo, obase + d4*4, acc4);
        }
    }
}

// ---------------- last-layer attention: only query row 0 per (b,h) ----------------
__global__ __launch_bounds__(128)
void attn_last_kernel()
{
    __shared__ float KV[NTOK*HD];
    __shared__ float Q[HD];
    __shared__ float P[NTOK];
    __shared__ float red[2];

    int bh = blockIdx.x;
    int b = bh >> 4, h = bh & 15;
    int tid = threadIdx.x;
    size_t base = (size_t)b*NTOK*3*DMODEL + (size_t)h*HD;

    if (h == 0) {
        for (int d = tid; d < DMODEL; d += 128)
            g_xp[(size_t)b*DMODEL + d] = g_x[(size_t)(b*NTOK)*DMODEL + d];
    }

    for (int idx = tid; idx < NTOK*32; idx += 128) {
        int n = idx >> 5, i = idx & 31;
        int ii = i & 15;
        int pos = (n == 0) ? 0 : ((i < 16) ? ((n-1) >> 3) : ((n-1) & 7));
        float ang = (float)pos * exp2f(-(float)ii * ROPE_L2);
        float cs = cosf(ang), sn = sinf(ang);
        float2 v = *(const float2*)(&g_qkv[base + (size_t)n*3*DMODEL + DMODEL + 2*i]);
        KV[n*HD + 2*i]   = v.x*cs - v.y*sn;
        KV[n*HD + 2*i+1] = v.y*cs + v.x*sn;
    }
    if (tid < HD) Q[tid] = g_qkv[base + tid];
    __syncthreads();

    if (tid < NTOK) {
        float acc = 0.f;
#pragma unroll
        for (int d = 0; d < HD; d++) acc += Q[d] * KV[tid*HD + d];
        P[tid] = acc * 0.125f;
    }
    __syncthreads();
    if (tid == 0) {
        float m = -1e30f;
        for (int j = 0; j < NTOK; j++) m = fmaxf(m, P[j]);
        red[0] = m;
    }
    __syncthreads();
    if (tid < NTOK) P[tid] = expf(P[tid] - red[0]);
    __syncthreads();
    if (tid == 0) {
        float s = 0.f;
        for (int j = 0; j < NTOK; j++) s += P[j];
        red[1] = 1.0f / s;
    }
    __syncthreads();
    if (tid < NTOK) P[tid] *= red[1];
    __syncthreads();

    for (int idx = tid; idx < NTOK*HD; idx += 128) {
        int n = idx >> 6, d = idx & 63;
        KV[idx] = g_qkv[base + (size_t)n*3*DMODEL + 2*DMODEL + d];
    }
    __syncthreads();

    if (tid < HD) {
        float acc = 0.f;
#pragma unroll 1
        for (int j = 0; j < NTOK; j++) acc += P[j] * KV[j*HD + tid];
        store_hilo1(g_Ahi, g_Alo, (size_t)b*DMODEL + h*HD + tid, acc);
    }
}

// ---------------- launch ----------------
extern "C" void kernel_launch(void* const* d_in, const int* in_sizes, int n_in,
                              void* d_out, int out_size)
{
    const float* img     = (const float*)d_in[0];
    const float* patch_W = (const float*)d_in[1];
    const float* patch_b = (const float*)d_in[2];
    const float* cls     = (const float*)d_in[3];
    const float* ln1_g   = (const float*)d_in[4];
    const float* ln1_b   = (const float*)d_in[5];
    const float* Wqkv    = (const float*)d_in[6];
    const float* Wproj   = (const float*)d_in[7];
    const float* bproj   = (const float*)d_in[8];
    const float* ln2_g   = (const float*)d_in[9];
    const float* ln2_b   = (const float*)d_in[10];
    const float* W1      = (const float*)d_in[11];
    const float* b1      = (const float*)d_in[12];
    const float* W2      = (const float*)d_in[13];
    const float* b2      = (const float*)d_in[14];
    const float* lnf_g   = (const float*)d_in[15];
    const float* lnf_b   = (const float*)d_in[16];
    float* out = (float*)d_out;

    cudaFuncSetAttribute(gemm_mma, cudaFuncAttributeMaxDynamicSharedMemorySize, GEMM_SMEM);

    float *x, *qkv, *xp;
    __nv_bfloat16 *Ahi, *Alo, *Mhi, *Mlo, *Bh, *Bl;
    __nv_bfloat16 *Wqh, *Wql, *Wph, *Wpl, *W1h, *W1l, *W2h, *W2l;
    cudaGetSymbolAddress((void**)&x,   g_x);
    cudaGetSymbolAddress((void**)&qkv, g_qkv);
    cudaGetSymbolAddress((void**)&xp,  g_xp);
    cudaGetSymbolAddress((void**)&Ahi, g_Ahi);
    cudaGetSymbolAddress((void**)&Alo, g_Alo);
    cudaGetSymbolAddress((void**)&Mhi, g_Mhi);
    cudaGetSymbolAddress((void**)&Mlo, g_Mlo);
    cudaGetSymbolAddress((void**)&Bh,  g_Bhi);
    cudaGetSymbolAddress((void**)&Bl,  g_Blo);
    cudaGetSymbolAddress((void**)&Wqh, g_Wqh);
    cudaGetSymbolAddress((void**)&Wql, g_Wql);
    cudaGetSymbolAddress((void**)&Wph, g_Wph);
    cudaGetSymbolAddress((void**)&Wpl, g_Wpl);
    cudaGetSymbolAddress((void**)&W1h, g_W1h);
    cudaGetSymbolAddress((void**)&W1l, g_W1l);
    cudaGetSymbolAddress((void**)&W2h, g_W2h);
    cudaGetSymbolAddress((void**)&W2l, g_W2l);

    float* xc  = xp;                    // 256x1024 compact cls residual
    float* xc2 = xp + 256*DMODEL;       // 256x1024 compact working buffer

    // ---- side stream: all weight conversions, forked from the main stream ----
    cudaStream_t s2;
    cudaStreamCreateWithFlags(&s2, cudaStreamNonBlocking);
    cudaEvent_t evFork, evPatch, evW[DEPTH];
    cudaEventCreateWithFlags(&evFork, cudaEventDisableTiming);
    cudaEventCreateWithFlags(&evPatch, cudaEventDisableTiming);
    for (int l = 0; l < DEPTH; l++)
        cudaEventCreateWithFlags(&evW[l], cudaEventDisableTiming);

    cudaEventRecord(evFork, 0);
    cudaStreamWaitEvent(s2, evFork, 0);

    wconv_kernel<<<dim3(DMODEL/32, 1024/32), dim3(32,8), 0, s2>>>(patch_W, Bh, Bl, 1024, DMODEL);
    cudaEventRecord(evPatch, s2);

    for (int l = 0; l < DEPTH; l++) {
        const float* wq = Wqkv  + (size_t)l*DMODEL*3*DMODEL;
        const float* wp = Wproj + (size_t)l*DMODEL*DMODEL;
        const float* w1 = W1    + (size_t)l*DMODEL*FF;
        const float* w2 = W2    + (size_t)l*FF*DMODEL;
        wconv_kernel<<<dim3(3*DMODEL/32, DMODEL/32), dim3(32,8), 0, s2>>>(
            wq, Wqh + (size_t)l*DMODEL*3*DMODEL, Wql + (size_t)l*DMODEL*3*DMODEL, DMODEL, 3*DMODEL);
        wconv_kernel<<<dim3(DMODEL/32, DMODEL/32), dim3(32,8), 0, s2>>>(
            wp, Wph + (size_t)l*DMODEL*DMODEL, Wpl + (size_t)l*DMODEL*DMODEL, DMODEL, DMODEL);
        wconv_kernel<<<dim3(FF/32, DMODEL/32), dim3(32,8), 0, s2>>>(
            w1, W1h + (size_t)l*DMODEL*FF, W1l + (size_t)l*DMODEL*FF, DMODEL, FF);
        wconv_kernel<<<dim3(DMODEL/32, FF/32), dim3(32,8), 0, s2>>>(
            w2, W2h + (size_t)l*FF*DMODEL, W2l + (size_t)l*FF*DMODEL, FF, DMODEL);
        cudaEventRecord(evW[l], s2);
    }

    // ---- main stream: patch embedding (scatter fused into GEMM epilogue) ----
    {
        int total = MPATCH * PSZ * PSZ;
        gather_kernel<<<(total+255)/256, 256>>>(img);
        assemble_cls_kernel<<<(BATCH*DMODEL+255)/256, 256>>>(cls);
        cudaStreamWaitEvent(0, evPatch, 0);
        gemm_mma<<<dim3(DMODEL/128, MPATCH/128), 256, GEMM_SMEM>>>(
            Mhi, Mlo, Bh, Bl, patch_b, nullptr, x, nullptr, nullptr,
            MPATCH, DMODEL, 1024, 5);
    }

    // ---- layers 0..10 (full) ----
    for (int l = 0; l < DEPTH-1; l++) {
        const __nv_bfloat16* wqh = Wqh + (size_t)l*DMODEL*3*DMODEL;
        const __nv_bfloat16* wql = Wql + (size_t)l*DMODEL*3*DMODEL;
        const __nv_bfloat16* wph = Wph + (size_t)l*DMODEL*DMODEL;
        const __nv_bfloat16* wpl = Wpl + (size_t)l*DMODEL*DMODEL;
        const __nv_bfloat16* w1h = W1h + (size_t)l*DMODEL*FF;
        const __nv_bfloat16* w1l = W1l + (size_t)l*DMODEL*FF;
        const __nv_bfloat16* w2h = W2h + (size_t)l*FF*DMODEL;
        const __nv_bfloat16* w2l = W2l + (size_t)l*FF*DMODEL;

        ln_kernel<<<BN_TOK, 128>>>(x, ln1_g + l*DMODEL, ln1_b + l*DMODEL, Ahi, Alo);

        cudaStreamWaitEvent(0, evW[l], 0);
        gemm_mma<<<dim3(3*DMODEL/128, BN_TOK/128), 256, GEMM_SMEM>>>(
            Ahi, Alo, wqh, wql, nullptr, nullptr, qkv, nullptr, nullptr,
            BN_TOK, 3*DMODEL, DMODEL, 0);

        attn_kernel<<<BATCH*HEADS, 128>>>();

        gemm_mma<<<dim3(DMODEL/128, BN_TOK/128), 256, GEMM_SMEM>>>(
            Ahi, Alo, wph, wpl, bproj + l*DMODEL, x, x, nullptr, nullptr,
            BN_TOK, DMODEL, DMODEL, 2);

        ln_kernel<<<BN_TOK, 128>>>(x, ln2_g + l*DMODEL, ln2_b + l*DMODEL, Ahi, Alo);

        gemm_mma<<<dim3(FF/128, BN_TOK/128), 256, GEMM_SMEM>>>(
            Ahi, Alo, w1h, w1l, b1 + l*FF, nullptr, nullptr, Mhi, Mlo,
            BN_TOK, FF, DMODEL, 3);

        gemm_mma<<<dim3(DMODEL/128, BN_TOK/128), 256, GEMM_SMEM>>>(
            Mhi, Mlo, w2h, w2l, b2 + l*DMODEL, x, x, nullptr, nullptr,
            BN_TOK, DMODEL, FF, 2);
    }

    // ---- layer 11 (only cls rows survive) ----
    {
        const int l = DEPTH-1;
        const __nv_bfloat16* wqh = Wqh + (size_t)l*DMODEL*3*DMODEL;
        const __nv_bfloat16* wql = Wql + (size_t)l*DMODEL*3*DMODEL;
        const __nv_bfloat16* wph = Wph + (size_t)l*DMODEL*DMODEL;
        const __nv_bfloat16* wpl = Wpl + (size_t)l*DMODEL*DMODEL;
        const __nv_bfloat16* w1h = W1h + (size_t)l*DMODEL*FF;
        const __nv_bfloat16* w1l = W1l + (size_t)l*DMODEL*FF;
        const __nv_bfloat16* w2h = W2h + (size_t)l*FF*DMODEL;
        const __nv_bfloat16* w2l = W2l + (size_t)l*FF*DMODEL;

        ln_kernel<<<BN_TOK, 128>>>(x, ln1_g + l*DMODEL, ln1_b + l*DMODEL, Ahi, Alo);
        cudaStreamWaitEvent(0, evW[l], 0);
        gemm_mma<<<dim3(3*DMODEL/128, BN_TOK/128), 256, GEMM_SMEM>>>(
            Ahi, Alo, wqh, wql, nullptr, nullptr, qkv, nullptr, nullptr,
            BN_TOK, 3*DMODEL, DMODEL, 0);

        attn_last_kernel<<<BATCH*HEADS, 128>>>();   // also fills xc (cls rows)

        gemm_mma<<<dim3(DMODEL/128, 2), 256, GEMM_SMEM>>>(
            Ahi, Alo, wph, wpl, bproj + l*DMODEL, xc, xc2, nullptr, nullptr,
            256, DMODEL, DMODEL, 2);

        ln_kernel<<<256, 128>>>(xc2, ln2_g + l*DMODEL, ln2_b + l*DMODEL, Ahi, Alo);

        gemm_mma<<<dim3(FF/128, 2), 256, GEMM_SMEM>>>(
            Ahi, Alo, w1h, w1l, b1 + l*FF, nullptr, nullptr, Mhi, Mlo,
            256, FF, DMODEL, 3);

        gemm_mma<<<dim3(DMODEL/128, 2), 256, GEMM_SMEM>>>(
            Mhi, Mlo, w2h, w2l, b2 + l*DMODEL, xc2, xc2, nullptr, nullptr,
            256, DMODEL, FF, 2);

        lnf_c_kernel<<<BATCH, 128>>>(xc2, lnf_g, lnf_b, out);
    }
}

// round 17
// speedup vs baseline: 1.0902x; 1.0453x over previous
#include <cuda_runtime.h>
#include <cuda_bf16.h>
#include <math.h>
#include <cstdint>

// ---------------- problem constants ----------------
#define BATCH   256
#define NTOK    65
#define BN_TOK  (BATCH*NTOK)      // 16640
#define HALF_B  (BATCH/2)         // 128
#define HALF_M  (HALF_B*NTOK)     // 8320 rows (= 65 tiles of 128)
#define DMODEL  1024
#define HEADS   16
#define HD      64
#define FF      4096
#define DEPTH   12
#define NPATCH  64
#define PSZ     32
#define IMGSZ   256
#define MPATCH  (BATCH*NPATCH)    // 16384

// ---------------- scratch ----------------
__device__ __align__(16) float g_x   [BN_TOK*DMODEL];
__device__ __align__(16) float g_qkv [BN_TOK*3*DMODEL];
__device__ __align__(16) float g_xp  [MPATCH*DMODEL];   // xc / xc2 compact buffers
__device__ __align__(16) __nv_bfloat16 g_Ahi[BN_TOK*DMODEL];
__device__ __align__(16) __nv_bfloat16 g_Alo[BN_TOK*DMODEL];
__device__ __align__(16) __nv_bfloat16 g_Mhi[BN_TOK*FF];
__device__ __align__(16) __nv_bfloat16 g_Mlo[BN_TOK*FF];
__device__ __align__(16) __nv_bfloat16 g_Bhi[DMODEL*DMODEL];   // patch weights only
__device__ __align__(16) __nv_bfloat16 g_Blo[DMODEL*DMODEL];

// per-layer pre-converted weights (side-stream targets)
__device__ __align__(16) __nv_bfloat16 g_Wqh[DEPTH*DMODEL*3*DMODEL];
__device__ __align__(16) __nv_bfloat16 g_Wql[DEPTH*DMODEL*3*DMODEL];
__device__ __align__(16) __nv_bfloat16 g_Wph[DEPTH*DMODEL*DMODEL];
__device__ __align__(16) __nv_bfloat16 g_Wpl[DEPTH*DMODEL*DMODEL];
__device__ __align__(16) __nv_bfloat16 g_W1h[DEPTH*DMODEL*FF];
__device__ __align__(16) __nv_bfloat16 g_W1l[DEPTH*DMODEL*FF];
__device__ __align__(16) __nv_bfloat16 g_W2h[DEPTH*FF*DMODEL];
__device__ __align__(16) __nv_bfloat16 g_W2l[DEPTH*FF*DMODEL];

// ---------------- PTX helpers (base-target sm_80+ only) ----------------
__device__ __forceinline__ uint32_t smem_u32(const void* p) {
    uint32_t a;
    asm("{ .reg .u64 t; cvta.to.shared.u64 t, %1; cvt.u32.u64 %0, t; }" : "=r"(a) : "l"(p));
    return a;
}
__device__ __forceinline__ void cpasync16(uint32_t dst, const void* src) {
    asm volatile("cp.async.cg.shared.global [%0], [%1], 16;" :: "r"(dst), "l"(src));
}
__device__ __forceinline__ void cpasync_commit() {
    asm volatile("cp.async.commit_group;" ::: "memory");
}
__device__ __forceinline__ void cpasync_wait0() {
    asm volatile("cp.async.wait_group 0;" ::: "memory");
}
__device__ __forceinline__ void cpasync_wait1() {
    asm volatile("cp.async.wait_group 1;" ::: "memory");
}
__device__ __forceinline__ void ldsm4(uint32_t* r, uint32_t addr) {
    asm volatile("ldmatrix.sync.aligned.m8n8.x4.shared.b16 {%0,%1,%2,%3}, [%4];"
                 : "=r"(r[0]), "=r"(r[1]), "=r"(r[2]), "=r"(r[3]) : "r"(addr));
}
__device__ __forceinline__ void mma16816(float* c, const uint32_t* a, const uint32_t* b) {
    asm volatile("mma.sync.aligned.m16n8k16.row.col.f32.bf16.bf16.f32 "
                 "{%0,%1,%2,%3}, {%4,%5,%6,%7}, {%8,%9}, {%0,%1,%2,%3};"
                 : "+f"(c[0]), "+f"(c[1]), "+f"(c[2]), "+f"(c[3])
                 : "r"(a[0]), "r"(a[1]), "r"(a[2]), "r"(a[3]), "r"(b[0]), "r"(b[1]));
}

// ---------------- small helpers ----------------
__device__ __forceinline__ float gelu_f(float v) {
    return 0.5f * v * (1.0f + erff(v * 0.70710678118654752440f));
}
__device__ __forceinline__ void store_hilo4(__nv_bfloat16* Hi, __nv_bfloat16* Lo, size_t idx, float4 v) {
    __nv_bfloat162 h0 = __floats2bfloat162_rn(v.x, v.y);
    __nv_bfloat162 h1 = __floats2bfloat162_rn(v.z, v.w);
    __nv_bfloat162 l0 = __floats2bfloat162_rn(v.x - __low2float(h0), v.y - __high2float(h0));
    __nv_bfloat162 l1 = __floats2bfloat162_rn(v.z - __low2float(h1), v.w - __high2float(h1));
    *reinterpret_cast<__nv_bfloat162*>(Hi + idx)     = h0;
    *reinterpret_cast<__nv_bfloat162*>(Hi + idx + 2) = h1;
    *reinterpret_cast<__nv_bfloat162*>(Lo + idx)     = l0;
    *reinterpret_cast<__nv_bfloat162*>(Lo + idx + 2) = l1;
}
__device__ __forceinline__ void store_hilo2(__nv_bfloat16* Hi, __nv_bfloat16* Lo, size_t idx, float v0, float v1) {
    __nv_bfloat162 h = __floats2bfloat162_rn(v0, v1);
    __nv_bfloat162 l = __floats2bfloat162_rn(v0 - __low2float(h), v1 - __high2float(h));
    *reinterpret_cast<__nv_bfloat162*>(Hi + idx) = h;
    *reinterpret_cast<__nv_bfloat162*>(Lo + idx) = l;
}
__device__ __forceinline__ void store_hilo1(__nv_bfloat16* Hi, __nv_bfloat16* Lo, size_t idx, float v) {
    __nv_bfloat16 h = __float2bfloat16(v);
    Hi[idx] = h;
    Lo[idx] = __float2bfloat16(v - __bfloat162float(h));
}

// ---------------- patch gather -> bf16 hi/lo rows [16384, 1024] ----------------
__global__ void gather_kernel(const float* __restrict__ img) {
    int idx = blockIdx.x * blockDim.x + threadIdx.x;
    const int total = MPATCH * PSZ * PSZ;
    if (idx >= total) return;
    int k = idx & 1023;
    int p = (idx >> 10) & 63;
    int b = idx >> 16;
    int i = k >> 5, j = k & 31;
    int gr = p >> 3, gc = p & 7;
    float v = img[(size_t)b*IMGSZ*IMGSZ + (size_t)(gr*PSZ + i)*IMGSZ + gc*PSZ + j];
    __nv_bfloat16 h = __float2bfloat16(v);
    g_Mhi[idx] = h;
    g_Mlo[idx] = __float2bfloat16(v - __bfloat162float(h));
}

// ---------------- write cls token rows of x ----------------
__global__ void assemble_cls_kernel(const float* __restrict__ cls) {
    int idx = blockIdx.x * blockDim.x + threadIdx.x;
    if (idx >= BATCH*DMODEL) return;
    int b = idx >> 10, d = idx & 1023;
    g_x[(size_t)(b*NTOK)*DMODEL + d] = cls[d];
}

// ---------------- weight transpose-convert: W[K,N] -> Bt[N,K] hi/lo bf16 ----------------
__global__ __launch_bounds__(256)
void wconv_kernel(const float* __restrict__ W, __nv_bfloat16* __restrict__ Bh,
                  __nv_bfloat16* __restrict__ Bl, int K, int N) {
    __shared__ float t[32][33];
    int n0 = blockIdx.x * 32, k0 = blockIdx.y * 32;
    int tx = threadIdx.x, ty = threadIdx.y;   // 32 x 8
#pragma unroll
    for (int i = 0; i < 32; i += 8)
        t[ty+i][tx] = W[(size_t)(k0+ty+i)*N + n0+tx];
    __syncthreads();
#pragma unroll
    for (int i = 0; i < 32; i += 8) {
        int n = ty + i;
        float v = t[tx][n];
        __nv_bfloat16 h = __float2bfloat16(v);
        size_t o = (size_t)(n0+n)*K + k0+tx;
        Bh[o] = h;
        Bl[o] = __float2bfloat16(v - __bfloat162float(h));
    }
}

// ---------------- mma.sync GEMM 128x128 (3xBF16 compensation) ----------------
// epi: 0 plain f32, 1 +bias, 2 +bias+residual, 3 +bias+gelu->hi/lo,
//      5 +bias with row remap row -> (row>>6)*65 + (row&63) + 1 (patch scatter).
#define TILEB  (128*64)                  // 8192 bytes per tile
#define STAGEB (4*TILEB)                 // 32768
#define NSTAGE 3
#define GEMM_SMEM (NSTAGE*STAGEB)        // 98304

__device__ __forceinline__ void load_stage(uint32_t sbase,
    const __nv_bfloat16* __restrict__ Ahi, const __nv_bfloat16* __restrict__ Alo,
    const __nv_bfloat16* __restrict__ Bhi, const __nv_bfloat16* __restrict__ Blo,
    int row0, int col0, int K, int k0, int tid)
{
#pragma unroll
    for (int i = 0; i < 2; i++) {
        int c   = tid + i*256;
        int row = c >> 2, lc = c & 3;
        uint32_t soff = (uint32_t)(row*64 + ((lc ^ ((row>>1)&3))*16));
        size_t ga = (size_t)(row0 + row)*K + k0 + lc*8;
        size_t gb = (size_t)(col0 + row)*K + k0 + lc*8;
        cpasync16(sbase +            soff, Ahi + ga);
        cpasync16(sbase +   TILEB +  soff, Alo + ga);
        cpasync16(sbase + 2*TILEB +  soff, Bhi + gb);
        cpasync16(sbase + 3*TILEB +  soff, Blo + gb);
    }
    cpasync_commit();
}

__global__ __launch_bounds__(256, 2)
void gemm_mma(const __nv_bfloat16* __restrict__ Ahi, const __nv_bfloat16* __restrict__ Alo,
              const __nv_bfloat16* __restrict__ Bhi, const __nv_bfloat16* __restrict__ Blo,
              const float* __restrict__ bias, const float* __restrict__ res,
              float* __restrict__ C, __nv_bfloat16* __restrict__ Ohi, __nv_bfloat16* __restrict__ Olo,
              int M, int Nn, int K, int epi)
{
    extern __shared__ char smem[];
    uint32_t sb = smem_u32(smem);
    int tid = threadIdx.x;
    int wid = tid >> 5, lane = tid & 31;
    int row0 = blockIdx.y * 128, col0 = blockIdx.x * 128;

    int wm = (wid & 1) * 64;
    int wn = (wid >> 1) * 32;

    int aRow = wm + (lane & 15);
    uint32_t aSw  = (uint32_t)(((aRow >> 1) & 3) << 4);
    uint32_t aKB  = (uint32_t)(((lane >> 4) & 1) << 4);
    uint32_t aBase = (uint32_t)(aRow * 64);
    int bRow = wn + (lane & 7) + ((lane >> 4) & 1) * 8;
    uint32_t bSw  = (uint32_t)(((bRow >> 1) & 3) << 4);
    uint32_t bKB  = (uint32_t)(((lane >> 3) & 1) << 4);
    uint32_t bBase = (uint32_t)(bRow * 64);

    float acc[4][4][4];
#pragma unroll
    for (int mt = 0; mt < 4; mt++)
#pragma unroll
        for (int nt = 0; nt < 4; nt++)
#pragma unroll
            for (int e = 0; e < 4; e++) acc[mt][nt][e] = 0.f;

    int NC = K >> 5;
    load_stage(sb, Ahi, Alo, Bhi, Blo, row0, col0, K, 0, tid);
    if (NC > 1)
        load_stage(sb + STAGEB, Ahi, Alo, Bhi, Blo, row0, col0, K, 32, tid);

    uint32_t stOff = 0;
    uint32_t ldOff = (NC > 1) ? 2u*STAGEB : STAGEB;

#pragma unroll 1
    for (int kc = 0; kc < NC; kc++) {
        if (kc + 1 < NC) cpasync_wait1(); else cpasync_wait0();
        __syncthreads();
        if (kc + 2 < NC) {
            load_stage(sb + ldOff, Ahi, Alo, Bhi, Blo, row0, col0, K, (kc + 2) << 5, tid);
        }
        uint32_t st = sb + stOff;
        stOff += STAGEB; if (stOff == NSTAGE*STAGEB) stOff = 0;
        ldOff += STAGEB; if (ldOff == NSTAGE*STAGEB) ldOff = 0;

#pragma unroll
        for (int ks2 = 0; ks2 < 2; ks2++) {
            uint32_t kadd = (uint32_t)ks2 * 32;
            uint32_t aLK = (kadd + aKB) ^ aSw;
            uint32_t bLK = (kadd + bKB) ^ bSw;
            uint32_t ah[4][4], bh[2][4], al[4][4], bl[2][4];
#pragma unroll
            for (int mt = 0; mt < 4; mt++)
                ldsm4(ah[mt], st + aBase + (uint32_t)mt*1024 + aLK);
#pragma unroll
            for (int ntp = 0; ntp < 2; ntp++)
                ldsm4(bh[ntp], st + 2*TILEB + bBase + (uint32_t)ntp*1024 + bLK);
#pragma unroll
            for (int mt = 0; mt < 4; mt++)
                ldsm4(al[mt], st + TILEB + aBase + (uint32_t)mt*1024 + aLK);
            // hi x hi
#pragma unroll
            for (int mt = 0; mt < 4; mt++)
#pragma unroll
                for (int nt = 0; nt < 4; nt++)
                    mma16816(acc[mt][nt], ah[mt], &bh[nt>>1][(nt&1)*2]);
#pragma unroll
            for (int ntp = 0; ntp < 2; ntp++)
                ldsm4(bl[ntp], st + 3*TILEB + bBase + (uint32_t)ntp*1024 + bLK);
            // lo x hi
#pragma unroll
            for (int mt = 0; mt < 4; mt++)
#pragma unroll
                for (int nt = 0; nt < 4; nt++)
                    mma16816(acc[mt][nt], al[mt], &bh[nt>>1][(nt&1)*2]);
            // hi x lo
#pragma unroll
            for (int mt = 0; mt < 4; mt++)
#pragma unroll
                for (int nt = 0; nt < 4; nt++)
                    mma16816(acc[mt][nt], ah[mt], &bl[nt>>1][(nt&1)*2]);
        }
    }

    // ---------------- epilogue ----------------
    int base_r = row0 + wm;
    int base_c = col0 + wn;
#pragma unroll
    for (int mt = 0; mt < 4; mt++) {
#pragma unroll
        for (int nt = 0; nt < 4; nt++) {
            int r = base_r + mt*16 + (lane >> 2);
            int c = base_c + nt*8 + (lane & 3)*2;
            float* a4 = acc[mt][nt];
#pragma unroll
            for (int half = 0; half < 2; half++) {
                int rr = r + half*8;
                float v0 = a4[half*2], v1 = a4[half*2+1];
                size_t off = (size_t)rr * Nn + c;
                if (epi == 5) off = (size_t)((rr >> 6)*NTOK + (rr & 63) + 1) * Nn + c;
                if (epi != 0) {
                    float2 bb = *reinterpret_cast<const float2*>(bias + c);
                    v0 += bb.x; v1 += bb.y;
                }
                if (epi == 3) {
                    v0 = gelu_f(v0); v1 = gelu_f(v1);
                    store_hilo2(Ohi, Olo, off, v0, v1);
                } else {
                    if (epi == 2) {
                        float2 rr2 = *reinterpret_cast<const float2*>(res + off);
                        v0 += rr2.x; v1 += rr2.y;
                    }
                    float2 o; o.x = v0; o.y = v1;
                    *reinterpret_cast<float2*>(C + off) = o;
                }
            }
        }
    }
}

// ---------------- layernorm -> bf16 hi/lo ----------------
__global__ __launch_bounds__(128)
void ln_kernel(const float* __restrict__ x, const float* __restrict__ g,
               const float* __restrict__ b, __nv_bfloat16* __restrict__ Ohi,
               __nv_bfloat16* __restrict__ Olo)
{
    int row = blockIdx.x;
    int tid = threadIdx.x;
    const float* xp = x + (size_t)row * DMODEL;
    float4 a = *(const float4*)(xp + tid*4);
    float4 c = *(const float4*)(xp + 512 + tid*4);
    float s  = a.x+a.y+a.z+a.w + c.x+c.y+c.z+c.w;
    float sq = a.x*a.x+a.y*a.y+a.z*a.z+a.w*a.w + c.x*c.x+c.y*c.y+c.z*c.z+c.w*c.w;
#pragma unroll
    for (int off = 16; off; off >>= 1) {
        s  += __shfl_xor_sync(0xffffffffu, s,  off);
        sq += __shfl_xor_sync(0xffffffffu, sq, off);
    }
    __shared__ float sm[8];
    int wid = tid >> 5, lane = tid & 31;
    if (lane == 0) { sm[wid] = s; sm[4+wid] = sq; }
    __syncthreads();
    s  = sm[0]+sm[1]+sm[2]+sm[3];
    sq = sm[4]+sm[5]+sm[6]+sm[7];
    float mu  = s * (1.f/DMODEL);
    float var = sq * (1.f/DMODEL) - mu*mu;
    float inv = rsqrtf(var + 1e-5f);

    int d0 = tid*4;
    float4 g0 = *(const float4*)(g + d0);
    float4 b0 = *(const float4*)(b + d0);
    float4 o0;
    o0.x = (a.x-mu)*inv*g0.x + b0.x; o0.y = (a.y-mu)*inv*g0.y + b0.y;
    o0.z = (a.z-mu)*inv*g0.z + b0.z; o0.w = (a.w-mu)*inv*g0.w + b0.w;
    store_hilo4(Ohi, Olo, (size_t)row*DMODEL + d0, o0);

    int d1 = 512 + tid*4;
    float4 g1 = *(const float4*)(g + d1);
    float4 b1 = *(const float4*)(b + d1);
    float4 o1;
    o1.x = (c.x-mu)*inv*g1.x + b1.x; o1.y = (c.y-mu)*inv*g1.y + b1.y;
    o1.z = (c.z-mu)*inv*g1.z + b1.z; o1.w = (c.w-mu)*inv*g1.w + b1.w;
    store_hilo4(Ohi, Olo, (size_t)row*DMODEL + d1, o1);
}

// ---------------- final layernorm on COMPACT cls buffer -> d_out (f32) ----------------
__global__ __launch_bounds__(128)
void lnf_c_kernel(const float* __restrict__ xc, const float* __restrict__ g,
                  const float* __restrict__ b, float* __restrict__ out)
{
    int row = blockIdx.x;
    int tid = threadIdx.x;
    const float* xp = xc + (size_t)row * DMODEL;
    float4 a = *(const float4*)(xp + tid*4);
    float4 c = *(const float4*)(xp + 512 + tid*4);
    float s  = a.x+a.y+a.z+a.w + c.x+c.y+c.z+c.w;
    float sq = a.x*a.x+a.y*a.y+a.z*a.z+a.w*a.w + c.x*c.x+c.y*c.y+c.z*c.z+c.w*c.w;
#pragma unroll
    for (int off = 16; off; off >>= 1) {
        s  += __shfl_xor_sync(0xffffffffu, s,  off);
        sq += __shfl_xor_sync(0xffffffffu, sq, off);
    }
    __shared__ float sm[8];
    int wid = tid >> 5, lane = tid & 31;
    if (lane == 0) { sm[wid] = s; sm[4+wid] = sq; }
    __syncthreads();
    s  = sm[0]+sm[1]+sm[2]+sm[3];
    sq = sm[4]+sm[5]+sm[6]+sm[7];
    float mu  = s * (1.f/DMODEL);
    float var = sq * (1.f/DMODEL) - mu*mu;
    float inv = rsqrtf(var + 1e-5f);

    int d0 = tid*4;
    float4 g0 = *(const float4*)(g + d0);
    float4 b0 = *(const float4*)(b + d0);
    float4 o0;
    o0.x = (a.x-mu)*inv*g0.x + b0.x; o0.y = (a.y-mu)*inv*g0.y + b0.y;
    o0.z = (a.z-mu)*inv*g0.z + b0.z; o0.w = (a.w-mu)*inv*g0.w + b0.w;
    *(float4*)(out + (size_t)row*DMODEL + d0) = o0;
    int d1 = 512 + tid*4;
    float4 g1 = *(const float4*)(g + d1);
    float4 b1 = *(const float4*)(b + d1);
    float4 o1;
    o1.x = (c.x-mu)*inv*g1.x + b1.x; o1.y = (c.y-mu)*inv*g1.y + b1.y;
    o1.z = (c.z-mu)*inv*g1.z + b1.z; o1.w = (c.w-mu)*inv*g1.w + b1.w;
    *(float4*)(out + (size_t)row*DMODEL + d1) = o1;
}

// ---------------- attention with fused RoPE: one block per (b,h); b offset by b0 ----------------
#define ROPE_L2 0.83048202372184059f

__global__ __launch_bounds__(128)
void attn_kernel(int b0)
{
    __shared__ float KV[NTOK*HD];
    __shared__ float Ss[NTOK*67];

    int bh = blockIdx.x;
    int b = b0 + (bh >> 4), h = bh & 15;
    int tid = threadIdx.x;
    size_t base = (size_t)b*NTOK*3*DMODEL + (size_t)h*HD;

    for (int idx = tid; idx < NTOK*32; idx += 128) {
        int n = idx >> 5, i = idx & 31;
        int ii = i & 15;
        int pos = (n == 0) ? 0 : ((i < 16) ? ((n-1) >> 3) : ((n-1) & 7));
        float ang = (float)pos * exp2f(-(float)ii * ROPE_L2);
        float cs = cosf(ang), sn = sinf(ang);
        float2 v = *(const float2*)(&g_qkv[base + (size_t)n*3*DMODEL + DMODEL + 2*i]);
        KV[n*HD + 2*i]   = v.x*cs - v.y*sn;
        KV[n*HD + 2*i+1] = v.y*cs + v.x*sn;
    }
    __syncthreads();

    int r = tid;
    float qreg[HD];
    if (r < NTOK) {
        const float* qp = &g_qkv[base + (size_t)r*3*DMODEL];
#pragma unroll
        for (int d4 = 0; d4 < 16; d4++) {
            float4 t4 = *(const float4*)(qp + d4*4);
            qreg[d4*4+0]=t4.x; qreg[d4*4+1]=t4.y; qreg[d4*4+2]=t4.z; qreg[d4*4+3]=t4.w;
        }
#pragma unroll
        for (int i = 0; i < 32; i++) {
            int ii = i & 15;
            int pos = (r == 0) ? 0 : ((i < 16) ? ((r-1) >> 3) : ((r-1) & 7));
            float ang = (float)pos * exp2f(-(float)ii * ROPE_L2);
            float cs = cosf(ang), sn = sinf(ang);
            float xe = qreg[2*i], xo = qreg[2*i+1];
            qreg[2*i]   = xe*cs - xo*sn;
            qreg[2*i+1] = xo*cs + xe*sn;
        }
#pragma unroll 1
        for (int j = 0; j < NTOK; j++) {
            float acc = 0.f;
#pragma unroll
            for (int d4 = 0; d4 < 16; d4++) {
                float4 kv = *(const float4*)(&KV[j*HD + d4*4]);
                acc += qreg[d4*4+0]*kv.x + qreg[d4*4+1]*kv.y
                     + qreg[d4*4+2]*kv.z + qreg[d4*4+3]*kv.w;
            }
            Ss[r*67 + j] = acc * 0.125f;
        }
        float m = -1e30f;
#pragma unroll 1
        for (int j = 0; j < NTOK; j++) m = fmaxf(m, Ss[r*67+j]);
        float sum = 0.f;
#pragma unroll 1
        for (int j = 0; j < NTOK; j++) {
            float e = expf(Ss[r*67+j] - m);
            Ss[r*67+j] = e;
            sum += e;
        }
        float invs = 1.0f / sum;
#pragma unroll 1
        for (int j = 0; j < NTOK; j++) Ss[r*67+j] *= invs;
    }
    __syncthreads();

    for (int idx = tid; idx < NTOK*HD; idx += 128) {
        int n = idx >> 6, d = idx & 63;
        KV[idx] = g_qkv[base + (size_t)n*3*DMODEL + 2*DMODEL + d];
    }
    __syncthreads();

    if (r < NTOK) {
        size_t obase = (size_t)(b*NTOK + r)*DMODEL + h*HD;
#pragma unroll 1
        for (int d4 = 0; d4 < 16; d4++) {
            float4 acc4 = make_float4(0.f,0.f,0.f,0.f);
#pragma unroll 5
            for (int j = 0; j < NTOK; j++) {
                float s = Ss[r*67 + j];
                float4 vv = *(const float4*)(&KV[j*HD + d4*4]);
                acc4.x += s*vv.x; acc4.y += s*vv.y;
                acc4.z += s*vv.z; acc4.w += s*vv.w;
            }
            store_hilo4(g_Ahi, g_Alo, obase + d4*4, acc4);
        }
    }
}

// ---------------- last-layer attention: only query row 0 per (b,h) ----------------
__global__ __launch_bounds__(128)
void attn_last_kernel()
{
    __shared__ float KV[NTOK*HD];
    __shared__ float Q[HD];
    __shared__ float P[NTOK];
    __shared__ float red[2];

    int bh = blockIdx.x;
    int b = bh >> 4, h = bh & 15;
    int tid = threadIdx.x;
    size_t base = (size_t)b*NTOK*3*DMODEL + (size_t)h*HD;

    if (h == 0) {
        for (int d = tid; d < DMODEL; d += 128)
            g_xp[(size_t)b*DMODEL + d] = g_x[(size_t)(b*NTOK)*DMODEL + d];
    }

    for (int idx = tid; idx < NTOK*32; idx += 128) {
        int n = idx >> 5, i = idx & 31;
        int ii = i & 15;
        int pos = (n == 0) ? 0 : ((i < 16) ? ((n-1) >> 3) : ((n-1) & 7));
        float ang = (float)pos * exp2f(-(float)ii * ROPE_L2);
        float cs = cosf(ang), sn = sinf(ang);
        float2 v = *(const float2*)(&g_qkv[base + (size_t)n*3*DMODEL + DMODEL + 2*i]);
        KV[n*HD + 2*i]   = v.x*cs - v.y*sn;
        KV[n*HD + 2*i+1] = v.y*cs + v.x*sn;
    }
    if (tid < HD) Q[tid] = g_qkv[base + tid];
    __syncthreads();

    if (tid < NTOK) {
        float acc = 0.f;
#pragma unroll
        for (int d = 0; d < HD; d++) acc += Q[d] * KV[tid*HD + d];
        P[tid] = acc * 0.125f;
    }
    __syncthreads();
    if (tid == 0) {
        float m = -1e30f;
        for (int j = 0; j < NTOK; j++) m = fmaxf(m, P[j]);
        red[0] = m;
    }
    __syncthreads();
    if (tid < NTOK) P[tid] = expf(P[tid] - red[0]);
    __syncthreads();
    if (tid == 0) {
        float s = 0.f;
        for (int j = 0; j < NTOK; j++) s += P[j];
        red[1] = 1.0f / s;
    }
    __syncthreads();
    if (tid < NTOK) P[tid] *= red[1];
    __syncthreads();

    for (int idx = tid; idx < NTOK*HD; idx += 128) {
        int n = idx >> 6, d = idx & 63;
        KV[idx] = g_qkv[base + (size_t)n*3*DMODEL + 2*DMODEL + d];
    }
    __syncthreads();

    if (tid < HD) {
        float acc = 0.f;
#pragma unroll 1
        for (int j = 0; j < NTOK; j++) acc += P[j] * KV[j*HD + tid];
        store_hilo1(g_Ahi, g_Alo, (size_t)b*DMODEL + h*HD + tid, acc);
    }
}

// ---------------- launch ----------------
extern "C" void kernel_launch(void* const* d_in, const int* in_sizes, int n_in,
                              void* d_out, int out_size)
{
    const float* img     = (const float*)d_in[0];
    const float* patch_W = (const float*)d_in[1];
    const float* patch_b = (const float*)d_in[2];
    const float* cls     = (const float*)d_in[3];
    const float* ln1_g   = (const float*)d_in[4];
    const float* ln1_b   = (const float*)d_in[5];
    const float* Wqkv    = (const float*)d_in[6];
    const float* Wproj   = (const float*)d_in[7];
    const float* bproj   = (const float*)d_in[8];
    const float* ln2_g   = (const float*)d_in[9];
    const float* ln2_b   = (const float*)d_in[10];
    const float* W1      = (const float*)d_in[11];
    const float* b1      = (const float*)d_in[12];
    const float* W2      = (const float*)d_in[13];
    const float* b2      = (const float*)d_in[14];
    const float* lnf_g   = (const float*)d_in[15];
    const float* lnf_b   = (const float*)d_in[16];
    float* out = (float*)d_out;

    cudaFuncSetAttribute(gemm_mma, cudaFuncAttributeMaxDynamicSharedMemorySize, GEMM_SMEM);

    float *x, *qkv, *xp;
    __nv_bfloat16 *Ahi, *Alo, *Mhi, *Mlo, *Bh, *Bl;
    __nv_bfloat16 *Wqh, *Wql, *Wph, *Wpl, *W1h, *W1l, *W2h, *W2l;
    cudaGetSymbolAddress((void**)&x,   g_x);
    cudaGetSymbolAddress((void**)&qkv, g_qkv);
    cudaGetSymbolAddress((void**)&xp,  g_xp);
    cudaGetSymbolAddress((void**)&Ahi, g_Ahi);
    cudaGetSymbolAddress((void**)&Alo, g_Alo);
    cudaGetSymbolAddress((void**)&Mhi, g_Mhi);
    cudaGetSymbolAddress((void**)&Mlo, g_Mlo);
    cudaGetSymbolAddress((void**)&Bh,  g_Bhi);
    cudaGetSymbolAddress((void**)&Bl,  g_Blo);
    cudaGetSymbolAddress((void**)&Wqh, g_Wqh);
    cudaGetSymbolAddress((void**)&Wql, g_Wql);
    cudaGetSymbolAddress((void**)&Wph, g_Wph);
    cudaGetSymbolAddress((void**)&Wpl, g_Wpl);
    cudaGetSymbolAddress((void**)&W1h, g_W1h);
    cudaGetSymbolAddress((void**)&W1l, g_W1l);
    cudaGetSymbolAddress((void**)&W2h, g_W2h);
    cudaGetSymbolAddress((void**)&W2l, g_W2l);

    float* xc  = xp;                    // 256x1024 compact cls residual
    float* xc2 = xp + 256*DMODEL;       // 256x1024 compact working buffer

    // ---- ONE auxiliary stream (same count as the passing R13/R15 config):
    // s2 first runs all weight conversions, then is reused as the half-1
    // compute stream (wconv->half1 ordering is implicit in-stream).
    cudaStream_t s2;
    cudaStreamCreateWithFlags(&s2, cudaStreamNonBlocking);
    cudaEvent_t evFork, evPatch, evFork2, evHalf1, evW[DEPTH];
    cudaEventCreateWithFlags(&evFork, cudaEventDisableTiming);
    cudaEventCreateWithFlags(&evPatch, cudaEventDisableTiming);
    cudaEventCreateWithFlags(&evFork2, cudaEventDisableTiming);
    cudaEventCreateWithFlags(&evHalf1, cudaEventDisableTiming);
    for (int l = 0; l < DEPTH; l++)
        cudaEventCreateWithFlags(&evW[l], cudaEventDisableTiming);

    cudaEventRecord(evFork, 0);
    cudaStreamWaitEvent(s2, evFork, 0);

    // s2: all weight conversions
    wconv_kernel<<<dim3(DMODEL/32, 1024/32), dim3(32,8), 0, s2>>>(patch_W, Bh, Bl, 1024, DMODEL);
    cudaEventRecord(evPatch, s2);
    for (int l = 0; l < DEPTH; l++) {
        const float* wq = Wqkv  + (size_t)l*DMODEL*3*DMODEL;
        const float* wp = Wproj + (size_t)l*DMODEL*DMODEL;
        const float* w1 = W1    + (size_t)l*DMODEL*FF;
        const float* w2 = W2    + (size_t)l*FF*DMODEL;
        wconv_kernel<<<dim3(3*DMODEL/32, DMODEL/32), dim3(32,8), 0, s2>>>(
            wq, Wqh + (size_t)l*DMODEL*3*DMODEL, Wql + (size_t)l*DMODEL*3*DMODEL, DMODEL, 3*DMODEL);
        wconv_kernel<<<dim3(DMODEL/32, DMODEL/32), dim3(32,8), 0, s2>>>(
            wp, Wph + (size_t)l*DMODEL*DMODEL, Wpl + (size_t)l*DMODEL*DMODEL, DMODEL, DMODEL);
        wconv_kernel<<<dim3(FF/32, DMODEL/32), dim3(32,8), 0, s2>>>(
            w1, W1h + (size_t)l*DMODEL*FF, W1l + (size_t)l*DMODEL*FF, DMODEL, FF);
        wconv_kernel<<<dim3(DMODEL/32, FF/32), dim3(32,8), 0, s2>>>(
            w2, W2h + (size_t)l*FF*DMODEL, W2l + (size_t)l*FF*DMODEL, FF, DMODEL);
        cudaEventRecord(evW[l], s2);
    }

    // ---- main stream: patch embedding (scatter fused into GEMM epilogue) ----
    {
        int total = MPATCH * PSZ * PSZ;
        gather_kernel<<<(total+255)/256, 256>>>(img);
        assemble_cls_kernel<<<(BATCH*DMODEL+255)/256, 256>>>(cls);
        cudaStreamWaitEvent(0, evPatch, 0);
        gemm_mma<<<dim3(DMODEL/128, MPATCH/128), 256, GEMM_SMEM>>>(
            Mhi, Mlo, Bh, Bl, patch_b, nullptr, x, nullptr, nullptr,
            MPATCH, DMODEL, 1024, 5);
    }

    // ---- fork batch halves: half 0 on stream 0, half 1 on s2 (after wconvs) ----
    cudaEventRecord(evFork2, 0);
    cudaStreamWaitEvent(s2, evFork2, 0);

    auto run_half = [&](cudaStream_t st, int halfIdx, bool needWaitW) {
        size_t R0 = (size_t)halfIdx * HALF_M;        // row offset
        int    B0 = halfIdx * HALF_B;                // batch offset
        for (int l = 0; l < DEPTH-1; l++) {
            const __nv_bfloat16* wqh = Wqh + (size_t)l*DMODEL*3*DMODEL;
            const __nv_bfloat16* wql = Wql + (size_t)l*DMODEL*3*DMODEL;
            const __nv_bfloat16* wph = Wph + (size_t)l*DMODEL*DMODEL;
            const __nv_bfloat16* wpl = Wpl + (size_t)l*DMODEL*DMODEL;
            const __nv_bfloat16* w1h = W1h + (size_t)l*DMODEL*FF;
            const __nv_bfloat16* w1l = W1l + (size_t)l*DMODEL*FF;
            const __nv_bfloat16* w2h = W2h + (size_t)l*FF*DMODEL;
            const __nv_bfloat16* w2l = W2l + (size_t)l*FF*DMODEL;

            ln_kernel<<<HALF_M, 128, 0, st>>>(x + R0*DMODEL, ln1_g + l*DMODEL, ln1_b + l*DMODEL,
                                              Ahi + R0*DMODEL, Alo + R0*DMODEL);

            if (needWaitW) cudaStreamWaitEvent(st, evW[l], 0);
            gemm_mma<<<dim3(3*DMODEL/128, HALF_M/128), 256, GEMM_SMEM, st>>>(
                Ahi + R0*DMODEL, Alo + R0*DMODEL, wqh, wql, nullptr, nullptr,
                qkv + R0*3*DMODEL, nullptr, nullptr, HALF_M, 3*DMODEL, DMODEL, 0);

            attn_kernel<<<HALF_B*HEADS, 128, 0, st>>>(B0);

            gemm_mma<<<dim3(DMODEL/128, HALF_M/128), 256, GEMM_SMEM, st>>>(
                Ahi + R0*DMODEL, Alo + R0*DMODEL, wph, wpl, bproj + l*DMODEL,
                x + R0*DMODEL, x + R0*DMODEL, nullptr, nullptr, HALF_M, DMODEL, DMODEL, 2);

            ln_kernel<<<HALF_M, 128, 0, st>>>(x + R0*DMODEL, ln2_g + l*DMODEL, ln2_b + l*DMODEL,
                                              Ahi + R0*DMODEL, Alo + R0*DMODEL);

            gemm_mma<<<dim3(FF/128, HALF_M/128), 256, GEMM_SMEM, st>>>(
                Ahi + R0*DMODEL, Alo + R0*DMODEL, w1h, w1l, b1 + l*FF, nullptr, nullptr,
                Mhi + R0*FF, Mlo + R0*FF, HALF_M, FF, DMODEL, 3);

            gemm_mma<<<dim3(DMODEL/128, HALF_M/128), 256, GEMM_SMEM, st>>>(
                Mhi + R0*FF, Mlo + R0*FF, w2h, w2l, b2 + l*DMODEL,
                x + R0*DMODEL, x + R0*DMODEL, nullptr, nullptr, HALF_M, DMODEL, FF, 2);
        }
        // layer 11: ln1 + qkv for this half
        {
            const int l = DEPTH-1;
            ln_kernel<<<HALF_M, 128, 0, st>>>(x + R0*DMODEL, ln1_g + l*DMODEL, ln1_b + l*DMODEL,
                                              Ahi + R0*DMODEL, Alo + R0*DMODEL);
            if (needWaitW) cudaStreamWaitEvent(st, evW[l], 0);
            gemm_mma<<<dim3(3*DMODEL/128, HALF_M/128), 256, GEMM_SMEM, st>>>(
                Ahi + R0*DMODEL, Alo + R0*DMODEL,
                Wqh + (size_t)l*DMODEL*3*DMODEL, Wql + (size_t)l*DMODEL*3*DMODEL,
                nullptr, nullptr, qkv + R0*3*DMODEL, nullptr, nullptr,
                HALF_M, 3*DMODEL, DMODEL, 0);
        }
    };

    run_half(s2, 1, false);   // s2: after all wconvs in-stream -> no evW waits needed
    run_half(0,  0, true);    // stream 0: cross-stream, needs evW waits

    // join: half 1's qkv must be complete before attn_last reads all batches
    cudaEventRecord(evHalf1, s2);
    cudaStreamWaitEvent(0, evHalf1, 0);

    // ---- layer 11 tail (compact, stream 0) ----
    {
        const int l = DEPTH-1;
        const __nv_bfloat16* wph = Wph + (size_t)l*DMODEL*DMODEL;
        const __nv_bfloat16* wpl = Wpl + (size_t)l*DMODEL*DMODEL;
        const __nv_bfloat16* w1h = W1h + (size_t)l*DMODEL*FF;
        const __nv_bfloat16* w1l = W1l + (size_t)l*DMODEL*FF;
        const __nv_bfloat16* w2h = W2h + (size_t)l*FF*DMODEL;
        const __nv_bfloat16* w2l = W2l + (size_t)l*FF*DMODEL;

        attn_last_kernel<<<BATCH*HEADS, 128>>>();   // also fills xc (cls rows)

        gemm_mma<<<dim3(DMODEL/128, 2), 256, GEMM_SMEM>>>(
            Ahi, Alo, wph, wpl, bproj + l*DMODEL, xc, xc2, nullptr, nullptr,
            256, DMODEL, DMODEL, 2);

        ln_kernel<<<256, 128>>>(xc2, ln2_g + l*DMODEL, ln2_b + l*DMODEL, Ahi, Alo);

        gemm_mma<<<dim3(FF/128, 2), 256, GEMM_SMEM>>>(
            Ahi, Alo, w1h, w1l, b1 + l*FF, nullptr, nullptr, Mhi, Mlo,
            256, FF, DMODEL, 3);

        gemm_mma<<<dim3(DMODEL/128, 2), 256, GEMM_SMEM>>>(
            Mhi, Mlo, w2h, w2l, b2 + l*DMODEL, xc2, xc2, nullptr, nullptr,
            256, DMODEL, FF, 2);

        lnf_c_kernel<<<BATCH, 128>>>(xc2, lnf_g, lnf_b, out);
    }
}